// round 5
// baseline (speedup 1.0000x reference)
#include <cuda_runtime.h>
#include <cstdint>
#include <math.h>

#define N_NODES 50000
#define N_EDGES 500000
#define HID 256
#define LAYERS 15

// ---------------------------------------------------------------- scratch
__device__ float g_h  [(size_t)N_NODES * HID];
__device__ float g_agg[(size_t)N_NODES * HID];
__device__ float g_out[(size_t)N_NODES * HID];
__device__ float g_z1 [(size_t)N_EDGES * HID];
__device__ float g_statsf[2 * HID];
// CSR
__device__ int g_deg[N_NODES];
__device__ int g_off[N_NODES + 1];
__device__ int g_pos[N_NODES];
__device__ int g_srcs[N_EDGES];

// ---------------------------------------------------------------- helpers
__device__ __forceinline__ float to_tf32(float x) {
    uint32_t u;
    asm("cvt.rna.tf32.f32 %0, %1;" : "=r"(u) : "f"(x));
    return __uint_as_float(u);
}
__device__ __forceinline__ void mma8(float* c, const float* a, const float* b) {
    asm volatile(
        "mma.sync.aligned.m16n8k8.row.col.f32.tf32.tf32.f32 "
        "{%0,%1,%2,%3}, {%4,%5,%6,%7}, {%8,%9}, {%0,%1,%2,%3};"
        : "+f"(c[0]), "+f"(c[1]), "+f"(c[2]), "+f"(c[3])
        : "r"(__float_as_uint(a[0])), "r"(__float_as_uint(a[1])),
          "r"(__float_as_uint(a[2])), "r"(__float_as_uint(a[3])),
          "r"(__float_as_uint(b[0])), "r"(__float_as_uint(b[1])));
}

// fragment-major smem layout
// A' : [kh2][wm4][mt2][lane32][v4]   (2048 floats / 16-K slab)
// B' : [kh2][wn4][lane32][nt8][v2]   (4096 floats / 16-K slab)
#define ASLAB 2048
#define BSLAB 4096
#define STAGE (ASLAB + BSLAB)          // 6144 floats
#define SMEM_BYTES (2 * STAGE * 4)     // 49152 B

__device__ __forceinline__ int a_off(int row, int k) {
    int wm = row >> 5, mt = (row >> 4) & 1, v0 = (row >> 3) & 1, lq = row & 7;
    int kh = k >> 3, v1 = (k >> 2) & 1, lr = k & 3;
    return (((kh * 4 + wm) * 2 + mt) * 32 + lq * 4 + lr) * 4 + v0 + 2 * v1;
}
__device__ __forceinline__ int b_off(int col, int k) {
    int wn = col >> 6, nt = (col >> 3) & 7, lq = col & 7;
    int kh = k >> 3, v1 = (k >> 2) & 1, lr = k & 3;
    return (((kh * 4 + wn) * 32 + lq * 4 + lr) * 8 + nt) * 2 + v1;
}

__device__ __forceinline__ void store_slab(float* As, float* Bs, int am, int aks,
                                           float4 ra, float4 rb0, float4 rb1) {
    float va[4]  = {ra.x, ra.y, ra.z, ra.w};
    float vb0[4] = {rb0.x, rb0.y, rb0.z, rb0.w};
    float vb1[4] = {rb1.x, rb1.y, rb1.z, rb1.w};
#pragma unroll
    for (int j = 0; j < 4; j++) {
        As[a_off(am, aks + j)]       = to_tf32(va[j]);
        Bs[b_off(am, aks + j)]       = to_tf32(vb0[j]);
        Bs[b_off(am + 128, aks + j)] = to_tf32(vb1[j]);
    }
}

__device__ __forceinline__ void mma_slab(const float* As, const float* Bs,
                                         int wm, int wn, int lane,
                                         float c[2][8][4]) {
#pragma unroll
    for (int kh = 0; kh < 2; kh++) {
        float4 b4[4];
        const float4* bp = (const float4*)(Bs + ((kh * 4 + wn) * 32 + lane) * 16);
#pragma unroll
        for (int q = 0; q < 4; q++) b4[q] = bp[q];
        const float* bf = (const float*)b4;      // bf[nt*2 + v]
#pragma unroll
        for (int mt = 0; mt < 2; mt++) {
            float4 a4 = *(const float4*)(As + (((kh * 4 + wm) * 2 + mt) * 32 + lane) * 4);
            float a[4] = {a4.x, a4.y, a4.z, a4.w};
#pragma unroll
            for (int nt = 0; nt < 8; nt++) {
                float bb[2] = {bf[nt * 2], bf[nt * 2 + 1]};
                mma8(c[mt][nt], a, bb);
            }
        }
    }
}

// ---------------------------------------------------------------- small kernels
__global__ void k_input_fc(const float* __restrict__ x, const float* __restrict__ Win) {
    int idx = blockIdx.x * blockDim.x + threadIdx.x;
    if (idx < 2 * HID) g_statsf[idx] = 0.f;
    if (idx < N_NODES) g_deg[idx] = 0;
    if (idx >= N_NODES * HID) return;
    int node = idx >> 8, c = idx & 255;
    g_h[idx] = x[node * 2] * Win[c * 2] + x[node * 2 + 1] * Win[c * 2 + 1];
}

__global__ void k_csr_count(const int* __restrict__ ei) {
    int e = blockIdx.x * blockDim.x + threadIdx.x;
    if (e >= N_EDGES) return;
    atomicAdd(&g_deg[__ldg(ei + N_EDGES + e)], 1);
}

__global__ void k_csr_scan() {     // 1 block, 1024 threads
    __shared__ int wsum[32];
    __shared__ int s_carry;
    int tid = threadIdx.x, lane = tid & 31, wid = tid >> 5;
    if (tid == 0) s_carry = 0;
    __syncthreads();
    for (int base = 0; base < N_NODES; base += 1024) {
        int i = base + tid;
        int v = (i < N_NODES) ? g_deg[i] : 0;
        int x = v;
#pragma unroll
        for (int d = 1; d < 32; d <<= 1) {
            int y = __shfl_up_sync(0xffffffffu, x, d);
            if (lane >= d) x += y;
        }
        if (lane == 31) wsum[wid] = x;
        __syncthreads();
        if (wid == 0) {
            int w = wsum[lane];
#pragma unroll
            for (int d = 1; d < 32; d <<= 1) {
                int y = __shfl_up_sync(0xffffffffu, w, d);
                if (lane >= d) w += y;
            }
            wsum[lane] = w;
        }
        __syncthreads();
        int carry = s_carry;
        int incl = x + (wid > 0 ? wsum[wid - 1] : 0);
        if (i < N_NODES) {
            int excl = carry + incl - v;
            g_off[i] = excl;
            g_pos[i] = excl;
        }
        __syncthreads();
        if (tid == 0) s_carry = carry + wsum[31];
        __syncthreads();
    }
    if (threadIdx.x == 0) g_off[N_NODES] = s_carry;
}

__global__ void k_csr_fill(const int* __restrict__ ei) {
    int e = blockIdx.x * blockDim.x + threadIdx.x;
    if (e >= N_EDGES) return;
    int d = __ldg(ei + N_EDGES + e);
    int p = atomicAdd(&g_pos[d], 1);
    g_srcs[p] = __ldg(ei + e);
}

// ---- gather: agg[n] = sum h[src]; warp/node; block 0 zeroes BN stats ----
__global__ void k_gather() {
    if (blockIdx.x == 0 && threadIdx.x < HID) {
        g_statsf[threadIdx.x] = 0.f;
        g_statsf[HID + threadIdx.x] = 0.f;
    }
    int gw = (blockIdx.x * blockDim.x + threadIdx.x) >> 5;
    int lane = threadIdx.x & 31;
    if (gw >= N_NODES) return;
    int beg = g_off[gw], end = g_off[gw + 1];
    float4 a0 = make_float4(0.f, 0.f, 0.f, 0.f);
    float4 a1 = make_float4(0.f, 0.f, 0.f, 0.f);
    float4 a2 = make_float4(0.f, 0.f, 0.f, 0.f);
    float4 a3 = make_float4(0.f, 0.f, 0.f, 0.f);
    int i = beg;
    for (; i + 1 < end; i += 2) {
        int s0 = __ldg(&g_srcs[i]);
        int s1 = __ldg(&g_srcs[i + 1]);
        const float4* h0 = (const float4*)(g_h + (size_t)s0 * HID);
        const float4* h1 = (const float4*)(g_h + (size_t)s1 * HID);
        float4 v0 = __ldg(h0 + lane), v1 = __ldg(h0 + lane + 32);
        float4 v2 = __ldg(h1 + lane), v3 = __ldg(h1 + lane + 32);
        a0.x += v0.x; a0.y += v0.y; a0.z += v0.z; a0.w += v0.w;
        a1.x += v1.x; a1.y += v1.y; a1.z += v1.z; a1.w += v1.w;
        a2.x += v2.x; a2.y += v2.y; a2.z += v2.z; a2.w += v2.w;
        a3.x += v3.x; a3.y += v3.y; a3.z += v3.z; a3.w += v3.w;
    }
    if (i < end) {
        int s0 = __ldg(&g_srcs[i]);
        const float4* h0 = (const float4*)(g_h + (size_t)s0 * HID);
        float4 v0 = __ldg(h0 + lane), v1 = __ldg(h0 + lane + 32);
        a0.x += v0.x; a0.y += v0.y; a0.z += v0.z; a0.w += v0.w;
        a1.x += v1.x; a1.y += v1.y; a1.z += v1.z; a1.w += v1.w;
    }
    a0.x += a2.x; a0.y += a2.y; a0.z += a2.z; a0.w += a2.w;
    a1.x += a3.x; a1.y += a3.y; a1.z += a3.z; a1.w += a3.w;
    float4* ap = (float4*)(g_agg + (size_t)gw * HID);
    ap[lane] = a0;
    ap[lane + 32] = a1;
}

// ---- BN finalize + apply fused: h += relu(out*sc + sh) ----
__global__ void k_bn_apply(const float* __restrict__ gm, const float* __restrict__ bt) {
    __shared__ float ssc[HID], ssh[HID];
    int tid = threadIdx.x;
    if (tid < HID) {
        float mean = g_statsf[tid] * (1.f / N_NODES);
        float var  = g_statsf[HID + tid] * (1.f / N_NODES) - mean * mean;
        float rstd = rsqrtf(var + 1e-5f);
        float sc = rstd * __ldg(gm + tid);
        ssc[tid] = sc;
        ssh[tid] = __ldg(bt + tid) - mean * sc;
    }
    __syncthreads();
    int idx = blockIdx.x * blockDim.x + tid;
    if (idx >= N_NODES * 64) return;
    int c0 = (idx & 63) * 4;
    float4 o  = ((const float4*)g_out)[idx];
    float4 sc = *(const float4*)(ssc + c0);
    float4 sh = *(const float4*)(ssh + c0);
    float4 hv = ((float4*)g_h)[idx];
    hv.x += fmaxf(fmaf(o.x, sc.x, sh.x), 0.f);
    hv.y += fmaxf(fmaf(o.y, sc.y, sh.y), 0.f);
    hv.z += fmaxf(fmaf(o.z, sc.z, sh.z), 0.f);
    hv.w += fmaxf(fmaf(o.w, sc.w, sh.w), 0.f);
    ((float4*)g_h)[idx] = hv;
}

// =================================================================
// pipelined tf32 mma.sync GEMM, fragment-major smem:
// 512 thr, 16 warps (4m x 4n), BM=128 BN=256 BK=16, warp tile 32x64
// =================================================================

// ---- node GEMM: out = agg@Wr^T + h@Wo^T + br, fused BN stats ----
__global__ void __launch_bounds__(512, 1)
k_gemm_node(const float* __restrict__ Wr, const float* __restrict__ Wo,
            const float* __restrict__ br) {
    extern __shared__ float sm[];
    int tid = threadIdx.x;
    int bm = blockIdx.x * 128;
    int lane = tid & 31, lq = lane >> 2, lr = lane & 3;
    int wid = tid >> 5, wm = wid & 3, wn = wid >> 2;
    int am = tid >> 2, aks = (tid & 3) * 4;
    int gr = bm + am;
    bool arow = gr < N_NODES;
    float c[2][8][4] = {};

    float4 ra, rb0, rb1;
    ra = arow ? __ldg((const float4*)(g_agg + (size_t)gr * HID + aks))
              : make_float4(0.f, 0.f, 0.f, 0.f);
    rb0 = __ldg((const float4*)(Wr + (size_t)am * HID + aks));
    rb1 = __ldg((const float4*)(Wr + (size_t)(am + 128) * HID + aks));

    for (int kt = 0; kt < 32; kt++) {
        int b = kt & 1;
        float* As = sm + b * STAGE;
        float* Bs = As + ASLAB;
        store_slab(As, Bs, am, aks, ra, rb0, rb1);
        float4 na = ra, nb0 = rb0, nb1 = rb1;
        if (kt < 31) {
            int k2 = kt + 1;
            int half = k2 >> 4, kc = (k2 & 15) * 16;
            const float* Asrc = half ? g_h : g_agg;
            const float* Bsrc = half ? Wo : Wr;
            na = arow ? __ldg((const float4*)(Asrc + (size_t)gr * HID + kc + aks))
                      : make_float4(0.f, 0.f, 0.f, 0.f);
            nb0 = __ldg((const float4*)(Bsrc + (size_t)am * HID + kc + aks));
            nb1 = __ldg((const float4*)(Bsrc + (size_t)(am + 128) * HID + kc + aks));
        }
        __syncthreads();
        mma_slab(As, Bs, wm, wn, lane, c);
        ra = na; rb0 = nb0; rb1 = nb1;
    }

    // epilogue: +br, store g_out, accumulate BN stats (fp32)
    float ps[8][2], pq[8][2];
#pragma unroll
    for (int nt = 0; nt < 8; nt++)
        ps[nt][0] = ps[nt][1] = pq[nt][0] = pq[nt][1] = 0.f;

#pragma unroll
    for (int mt = 0; mt < 2; mt++) {
        int row = bm + wm * 32 + mt * 16 + lq;
        bool v0 = row < N_NODES, v1 = (row + 8) < N_NODES;
#pragma unroll
        for (int nt = 0; nt < 8; nt++) {
            int col = wn * 64 + nt * 8 + lr * 2;
            float2 bb = __ldg((const float2*)(br + col));
            float o0 = c[mt][nt][0] + bb.x, o1 = c[mt][nt][1] + bb.y;
            float o2 = c[mt][nt][2] + bb.x, o3 = c[mt][nt][3] + bb.y;
            if (v0) {
                *(float2*)(g_out + (size_t)row * HID + col) = make_float2(o0, o1);
                ps[nt][0] += o0; pq[nt][0] += o0 * o0;
                ps[nt][1] += o1; pq[nt][1] += o1 * o1;
            }
            if (v1) {
                *(float2*)(g_out + (size_t)(row + 8) * HID + col) = make_float2(o2, o3);
                ps[nt][0] += o2; pq[nt][0] += o2 * o2;
                ps[nt][1] += o3; pq[nt][1] += o3 * o3;
            }
        }
    }
#pragma unroll
    for (int nt = 0; nt < 8; nt++)
#pragma unroll
        for (int u = 0; u < 2; u++) {
#pragma unroll
            for (int d = 4; d < 32; d <<= 1) {
                ps[nt][u] += __shfl_xor_sync(0xffffffffu, ps[nt][u], d);
                pq[nt][u] += __shfl_xor_sync(0xffffffffu, pq[nt][u], d);
            }
        }
    if (lq == 0) {
#pragma unroll
        for (int nt = 0; nt < 8; nt++) {
            int col = wn * 64 + nt * 8 + lr * 2;
            atomicAdd(&g_statsf[col], ps[nt][0]);
            atomicAdd(&g_statsf[col + 1], ps[nt][1]);
            atomicAdd(&g_statsf[HID + col], pq[nt][0]);
            atomicAdd(&g_statsf[HID + col + 1], pq[nt][1]);
        }
    }
}

// ---- edge GEMM1: z1 = relu(cat(h[src],h[dst]) @ W1^T + b1) ----
__global__ void __launch_bounds__(512, 1)
k_gemm_edge1(const int* __restrict__ ei, const float* __restrict__ W1,
             const float* __restrict__ b1) {
    extern __shared__ float sm[];
    int tid = threadIdx.x;
    int bm = blockIdx.x * 128;
    int lane = tid & 31, lq = lane >> 2, lr = lane & 3;
    int wid = tid >> 5, wm = wid & 3, wn = wid >> 2;
    int am = tid >> 2, aks = (tid & 3) * 4;
    int e = bm + am;
    bool val = e < N_EDGES;
    int nsrc = val ? __ldg(ei + e) : 0;
    int ndst = val ? __ldg(ei + N_EDGES + e) : 0;
    float c[2][8][4] = {};

    float4 ra, rb0, rb1;
    ra = val ? __ldg((const float4*)(g_h + (size_t)nsrc * HID + aks))
             : make_float4(0.f, 0.f, 0.f, 0.f);
    rb0 = __ldg((const float4*)(W1 + (size_t)am * 512 + aks));
    rb1 = __ldg((const float4*)(W1 + (size_t)(am + 128) * 512 + aks));

    for (int kt = 0; kt < 32; kt++) {
        int b = kt & 1;
        float* As = sm + b * STAGE;
        float* Bs = As + ASLAB;
        store_slab(As, Bs, am, aks, ra, rb0, rb1);
        float4 na = ra, nb0 = rb0, nb1 = rb1;
        if (kt < 31) {
            int k2 = kt + 1;
            int half = k2 >> 4, kc = (k2 & 15) * 16;
            int node = half ? ndst : nsrc;
            na = val ? __ldg((const float4*)(g_h + (size_t)node * HID + kc + aks))
                     : make_float4(0.f, 0.f, 0.f, 0.f);
            nb0 = __ldg((const float4*)(W1 + (size_t)am * 512 + k2 * 16 + aks));
            nb1 = __ldg((const float4*)(W1 + (size_t)(am + 128) * 512 + k2 * 16 + aks));
        }
        __syncthreads();
        mma_slab(As, Bs, wm, wn, lane, c);
        ra = na; rb0 = nb0; rb1 = nb1;
    }
#pragma unroll
    for (int mt = 0; mt < 2; mt++) {
        int row = bm + wm * 32 + mt * 16 + lq;
#pragma unroll
        for (int nt = 0; nt < 8; nt++) {
            int col = wn * 64 + nt * 8 + lr * 2;
            float2 bb = __ldg((const float2*)(b1 + col));
            if (row < N_EDGES) {
                float2 o = make_float2(fmaxf(c[mt][nt][0] + bb.x, 0.f),
                                       fmaxf(c[mt][nt][1] + bb.y, 0.f));
                *(float2*)(g_z1 + (size_t)row * HID + col) = o;
            }
            if (row + 8 < N_EDGES) {
                float2 o = make_float2(fmaxf(c[mt][nt][2] + bb.x, 0.f),
                                       fmaxf(c[mt][nt][3] + bb.y, 0.f));
                *(float2*)(g_z1 + (size_t)(row + 8) * HID + col) = o;
            }
        }
    }
}

// ---- edge GEMM2 + GEMV3 + sigmoid ----
__global__ void __launch_bounds__(512, 1)
k_gemm_edge2(const float* __restrict__ W2, const float* __restrict__ b2,
             const float* __restrict__ W3, const float* __restrict__ b3,
             float* __restrict__ dout) {
    extern __shared__ float sm[];
    __shared__ float sred[4][128];
    int tid = threadIdx.x;
    int bm = blockIdx.x * 128;
    int lane = tid & 31, lq = lane >> 2, lr = lane & 3;
    int wid = tid >> 5, wm = wid & 3, wn = wid >> 2;
    int am = tid >> 2, aks = (tid & 3) * 4;
    int e = bm + am;
    bool val = e < N_EDGES;
    float c[2][8][4] = {};

    float4 ra, rb0, rb1;
    ra = val ? __ldg((const float4*)(g_z1 + (size_t)e * HID + aks))
             : make_float4(0.f, 0.f, 0.f, 0.f);
    rb0 = __ldg((const float4*)(W2 + (size_t)am * HID + aks));
    rb1 = __ldg((const float4*)(W2 + (size_t)(am + 128) * HID + aks));

    for (int kt = 0; kt < 16; kt++) {
        int b = kt & 1;
        float* As = sm + b * STAGE;
        float* Bs = As + ASLAB;
        store_slab(As, Bs, am, aks, ra, rb0, rb1);
        float4 na = ra, nb0 = rb0, nb1 = rb1;
        if (kt < 15) {
            int kc = (kt + 1) * 16;
            na = val ? __ldg((const float4*)(g_z1 + (size_t)e * HID + kc + aks))
                     : make_float4(0.f, 0.f, 0.f, 0.f);
            nb0 = __ldg((const float4*)(W2 + (size_t)am * HID + kc + aks));
            nb1 = __ldg((const float4*)(W2 + (size_t)(am + 128) * HID + kc + aks));
        }
        __syncthreads();
        mma_slab(As, Bs, wm, wn, lane, c);
        ra = na; rb0 = nb0; rb1 = nb1;
    }

#pragma unroll
    for (int mt = 0; mt < 2; mt++) {
        float p0 = 0.f, p1 = 0.f;
#pragma unroll
        for (int nt = 0; nt < 8; nt++) {
            int col = wn * 64 + nt * 8 + lr * 2;
            float2 bb = __ldg((const float2*)(b2 + col));
            float2 ww = __ldg((const float2*)(W3 + col));
            p0 = fmaf(fmaxf(c[mt][nt][0] + bb.x, 0.f), ww.x, p0);
            p0 = fmaf(fmaxf(c[mt][nt][1] + bb.y, 0.f), ww.y, p0);
            p1 = fmaf(fmaxf(c[mt][nt][2] + bb.x, 0.f), ww.x, p1);
            p1 = fmaf(fmaxf(c[mt][nt][3] + bb.y, 0.f), ww.y, p1);
        }
        p0 += __shfl_xor_sync(0xffffffffu, p0, 1);
        p0 += __shfl_xor_sync(0xffffffffu, p0, 2);
        p1 += __shfl_xor_sync(0xffffffffu, p1, 1);
        p1 += __shfl_xor_sync(0xffffffffu, p1, 2);
        if (lr == 0) {
            sred[wn][wm * 32 + mt * 16 + lq] = p0;
            sred[wn][wm * 32 + mt * 16 + lq + 8] = p1;
        }
    }
    __syncthreads();
    if (tid < 128) {
        int gr = bm + tid;
        if (gr < N_EDGES) {
            float s = sred[0][tid] + sred[1][tid] + sred[2][tid] + sred[3][tid] + __ldg(b3);
            dout[gr] = 1.f / (1.f + expf(-s));
        }
    }
}

// ---------------------------------------------------------------- launch
extern "C" void kernel_launch(void* const* d_in, const int* in_sizes, int n_in,
                              void* d_out, int out_size) {
    const float* x     = (const float*)d_in[0];
    const int*   ei    = (const int*)  d_in[1];
    const float* Win   = (const float*)d_in[2];
    const float* Wrel  = (const float*)d_in[3];
    const float* brel  = (const float*)d_in[4];
    const float* Wroot = (const float*)d_in[5];
    const float* gamma = (const float*)d_in[6];
    const float* beta  = (const float*)d_in[7];
    const float* W1    = (const float*)d_in[8];
    const float* b1    = (const float*)d_in[9];
    const float* W2    = (const float*)d_in[10];
    const float* b2    = (const float*)d_in[11];
    const float* W3    = (const float*)d_in[12];
    const float* b3    = (const float*)d_in[13];
    float* out = (float*)d_out;

    cudaFuncSetAttribute(k_gemm_node,  cudaFuncAttributeMaxDynamicSharedMemorySize, SMEM_BYTES);
    cudaFuncSetAttribute(k_gemm_edge1, cudaFuncAttributeMaxDynamicSharedMemorySize, SMEM_BYTES);
    cudaFuncSetAttribute(k_gemm_edge2, cudaFuncAttributeMaxDynamicSharedMemorySize, SMEM_BYTES);

    k_input_fc<<<(N_NODES * HID + 255) / 256, 256>>>(x, Win);
    k_csr_count<<<(N_EDGES + 255) / 256, 256>>>(ei);
    k_csr_scan<<<1, 1024>>>();
    k_csr_fill<<<(N_EDGES + 255) / 256, 256>>>(ei);

    int node_grid = (N_NODES + 127) / 128;     // 391
    int gather_grid = (N_NODES * 32 + 255) / 256;
    for (int l = 0; l < LAYERS; l++) {
        k_gather<<<gather_grid, 256>>>();
        k_gemm_node<<<node_grid, 512, SMEM_BYTES>>>(
            Wrel + (size_t)l * HID * HID, Wroot + (size_t)l * HID * HID,
            brel + (size_t)l * HID);
        k_bn_apply<<<(N_NODES * 64 + 255) / 256, 256>>>(
            gamma + (size_t)l * HID, beta + (size_t)l * HID);
    }

    int edge_grid = (N_EDGES + 127) / 128;     // 3907
    k_gemm_edge1<<<edge_grid, 512, SMEM_BYTES>>>(ei, W1, b1);
    k_gemm_edge2<<<edge_grid, 512, SMEM_BYTES>>>(W2, b2, W3, b3, out);
}

// round 6
// speedup vs baseline: 3.6909x; 3.6909x over previous
#include <cuda_runtime.h>
#include <cuda_fp16.h>
#include <cstdint>
#include <math.h>

#define N_NODES 50000
#define N_EDGES 500000
#define HID 256
#define LAYERS 15

// ---------------------------------------------------------------- scratch
__device__ float g_h  [(size_t)N_NODES * HID];
__device__ float g_agg[(size_t)N_NODES * HID];
__device__ float g_out[(size_t)N_NODES * HID];
__device__ float g_z1 [(size_t)N_EDGES * HID];
__device__ float g_statsf[2 * HID];
// CSR
__device__ int g_deg[N_NODES];
__device__ int g_off[N_NODES + 1];
__device__ int g_pos[N_NODES];
__device__ int g_srcs[N_EDGES];

// ---------------------------------------------------------------- helpers
__device__ __forceinline__ uint32_t pack_h2(float x, float y) {
    __half2 h = __float22half2_rn(make_float2(x, y));
    return *(uint32_t*)&h;
}
// D(16x8,f32) += A(16x16,f16) * B(16x8,f16)
__device__ __forceinline__ void mma16(float* c, uint32_t a0, uint32_t a1,
                                      uint32_t a2, uint32_t a3,
                                      uint32_t b0, uint32_t b1) {
    asm volatile(
        "mma.sync.aligned.m16n8k16.row.col.f32.f16.f16.f32 "
        "{%0,%1,%2,%3}, {%4,%5,%6,%7}, {%8,%9}, {%0,%1,%2,%3};"
        : "+f"(c[0]), "+f"(c[1]), "+f"(c[2]), "+f"(c[3])
        : "r"(a0), "r"(a1), "r"(a2), "r"(a3), "r"(b0), "r"(b1));
}

// smem (uint32 = half2 units):  A2[k2 8][row 128]  B2[k2 8][col 256]
// strides ≡ 8 (mod 32) -> conflict-free fragment loads
#define ASTR2 136
#define BSTR2 264
#define ASLAB (8 * ASTR2)              // 1088
#define BSLAB (8 * BSTR2)              // 2112
#define STAGE (ASLAB + BSLAB)          // 3200 uints
#define SMEM_BYTES (2 * STAGE * 4)     // 25600 B

__device__ __forceinline__ void store_slab(uint32_t* As, uint32_t* Bs, int am, int aks,
                                           float4 ra, float4 rb0, float4 rb1) {
    int k2 = aks >> 1;                 // (tid&3)*2
    As[(k2 + 0) * ASTR2 + am] = pack_h2(ra.x, ra.y);
    As[(k2 + 1) * ASTR2 + am] = pack_h2(ra.z, ra.w);
    Bs[(k2 + 0) * BSTR2 + am] = pack_h2(rb0.x, rb0.y);
    Bs[(k2 + 1) * BSTR2 + am] = pack_h2(rb0.z, rb0.w);
    Bs[(k2 + 0) * BSTR2 + am + 128] = pack_h2(rb1.x, rb1.y);
    Bs[(k2 + 1) * BSTR2 + am + 128] = pack_h2(rb1.z, rb1.w);
}

// one 16-K slab: 2 mt x 8 nt m16n8k16
__device__ __forceinline__ void mma_slab(const uint32_t* As, const uint32_t* Bs,
                                         int wm, int wn, int lane,
                                         float c[2][8][4]) {
    int g = lane >> 2, t = lane & 3;
    uint32_t b0[8], b1[8];
#pragma unroll
    for (int nt = 0; nt < 8; nt++) {
        int C = wn * 64 + nt * 8 + g;
        b0[nt] = Bs[t * BSTR2 + C];
        b1[nt] = Bs[(t + 4) * BSTR2 + C];
    }
#pragma unroll
    for (int mt = 0; mt < 2; mt++) {
        int R = wm * 32 + mt * 16 + g;
        uint32_t a0 = As[t * ASTR2 + R];
        uint32_t a1 = As[t * ASTR2 + R + 8];
        uint32_t a2 = As[(t + 4) * ASTR2 + R];
        uint32_t a3 = As[(t + 4) * ASTR2 + R + 8];
#pragma unroll
        for (int nt = 0; nt < 8; nt++)
            mma16(c[mt][nt], a0, a1, a2, a3, b0[nt], b1[nt]);
    }
}

// ---------------------------------------------------------------- small kernels
__global__ void k_input_fc(const float* __restrict__ x, const float* __restrict__ Win) {
    int idx = blockIdx.x * blockDim.x + threadIdx.x;
    if (idx < 2 * HID) g_statsf[idx] = 0.f;
    if (idx < N_NODES) g_deg[idx] = 0;
    if (idx >= N_NODES * HID) return;
    int node = idx >> 8, c = idx & 255;
    g_h[idx] = x[node * 2] * Win[c * 2] + x[node * 2 + 1] * Win[c * 2 + 1];
}

__global__ void k_csr_count(const int* __restrict__ ei) {
    int e = blockIdx.x * blockDim.x + threadIdx.x;
    if (e >= N_EDGES) return;
    atomicAdd(&g_deg[__ldg(ei + N_EDGES + e)], 1);
}

__global__ void k_csr_scan() {     // 1 block, 1024 threads
    __shared__ int wsum[32];
    __shared__ int s_carry;
    int tid = threadIdx.x, lane = tid & 31, wid = tid >> 5;
    if (tid == 0) s_carry = 0;
    __syncthreads();
    for (int base = 0; base < N_NODES; base += 1024) {
        int i = base + tid;
        int v = (i < N_NODES) ? g_deg[i] : 0;
        int x = v;
#pragma unroll
        for (int d = 1; d < 32; d <<= 1) {
            int y = __shfl_up_sync(0xffffffffu, x, d);
            if (lane >= d) x += y;
        }
        if (lane == 31) wsum[wid] = x;
        __syncthreads();
        if (wid == 0) {
            int w = wsum[lane];
#pragma unroll
            for (int d = 1; d < 32; d <<= 1) {
                int y = __shfl_up_sync(0xffffffffu, w, d);
                if (lane >= d) w += y;
            }
            wsum[lane] = w;
        }
        __syncthreads();
        int carry = s_carry;
        int incl = x + (wid > 0 ? wsum[wid - 1] : 0);
        if (i < N_NODES) {
            int excl = carry + incl - v;
            g_off[i] = excl;
            g_pos[i] = excl;
        }
        __syncthreads();
        if (tid == 0) s_carry = carry + wsum[31];
        __syncthreads();
    }
    if (threadIdx.x == 0) g_off[N_NODES] = s_carry;
}

__global__ void k_csr_fill(const int* __restrict__ ei) {
    int e = blockIdx.x * blockDim.x + threadIdx.x;
    if (e >= N_EDGES) return;
    int d = __ldg(ei + N_EDGES + e);
    int p = atomicAdd(&g_pos[d], 1);
    g_srcs[p] = __ldg(ei + e);
}

// ---- gather: agg[n] = sum h[src]; warp/node; block 0 zeroes BN stats ----
__global__ void k_gather() {
    if (blockIdx.x == 0 && threadIdx.x < HID) {
        g_statsf[threadIdx.x] = 0.f;
        g_statsf[HID + threadIdx.x] = 0.f;
    }
    int gw = (blockIdx.x * blockDim.x + threadIdx.x) >> 5;
    int lane = threadIdx.x & 31;
    if (gw >= N_NODES) return;
    int beg = g_off[gw], end = g_off[gw + 1];
    float4 a0 = make_float4(0.f, 0.f, 0.f, 0.f);
    float4 a1 = make_float4(0.f, 0.f, 0.f, 0.f);
    float4 a2 = make_float4(0.f, 0.f, 0.f, 0.f);
    float4 a3 = make_float4(0.f, 0.f, 0.f, 0.f);
    int i = beg;
    for (; i + 1 < end; i += 2) {
        int s0 = __ldg(&g_srcs[i]);
        int s1 = __ldg(&g_srcs[i + 1]);
        const float4* h0 = (const float4*)(g_h + (size_t)s0 * HID);
        const float4* h1 = (const float4*)(g_h + (size_t)s1 * HID);
        float4 v0 = __ldg(h0 + lane), v1 = __ldg(h0 + lane + 32);
        float4 v2 = __ldg(h1 + lane), v3 = __ldg(h1 + lane + 32);
        a0.x += v0.x; a0.y += v0.y; a0.z += v0.z; a0.w += v0.w;
        a1.x += v1.x; a1.y += v1.y; a1.z += v1.z; a1.w += v1.w;
        a2.x += v2.x; a2.y += v2.y; a2.z += v2.z; a2.w += v2.w;
        a3.x += v3.x; a3.y += v3.y; a3.z += v3.z; a3.w += v3.w;
    }
    if (i < end) {
        int s0 = __ldg(&g_srcs[i]);
        const float4* h0 = (const float4*)(g_h + (size_t)s0 * HID);
        float4 v0 = __ldg(h0 + lane), v1 = __ldg(h0 + lane + 32);
        a0.x += v0.x; a0.y += v0.y; a0.z += v0.z; a0.w += v0.w;
        a1.x += v1.x; a1.y += v1.y; a1.z += v1.z; a1.w += v1.w;
    }
    a0.x += a2.x; a0.y += a2.y; a0.z += a2.z; a0.w += a2.w;
    a1.x += a3.x; a1.y += a3.y; a1.z += a3.z; a1.w += a3.w;
    float4* ap = (float4*)(g_agg + (size_t)gw * HID);
    ap[lane] = a0;
    ap[lane + 32] = a1;
}

// ---- BN finalize + apply fused: h += relu(out*sc + sh) ----
__global__ void k_bn_apply(const float* __restrict__ gm, const float* __restrict__ bt) {
    __shared__ float ssc[HID], ssh[HID];
    int tid = threadIdx.x;
    if (tid < HID) {
        float mean = g_statsf[tid] * (1.f / N_NODES);
        float var  = g_statsf[HID + tid] * (1.f / N_NODES) - mean * mean;
        float rstd = rsqrtf(var + 1e-5f);
        float sc = rstd * __ldg(gm + tid);
        ssc[tid] = sc;
        ssh[tid] = __ldg(bt + tid) - mean * sc;
    }
    __syncthreads();
    int idx = blockIdx.x * blockDim.x + tid;
    if (idx >= N_NODES * 64) return;
    int c0 = (idx & 63) * 4;
    float4 o  = ((const float4*)g_out)[idx];
    float4 sc = *(const float4*)(ssc + c0);
    float4 sh = *(const float4*)(ssh + c0);
    float4 hv = ((float4*)g_h)[idx];
    hv.x += fmaxf(fmaf(o.x, sc.x, sh.x), 0.f);
    hv.y += fmaxf(fmaf(o.y, sc.y, sh.y), 0.f);
    hv.z += fmaxf(fmaf(o.z, sc.z, sh.z), 0.f);
    hv.w += fmaxf(fmaf(o.w, sc.w, sh.w), 0.f);
    ((float4*)g_h)[idx] = hv;
}

// =================================================================
// pipelined fp16 mma.sync GEMM: 512 thr, 16 warps (4m x 4n),
// BM=128 BN=256 BK=16, warp tile 32x64, double-buffered smem
// =================================================================

// ---- node GEMM: out = agg@Wr^T + h@Wo^T + br, fused BN stats ----
__global__ void __launch_bounds__(512, 1)
k_gemm_node(const float* __restrict__ Wr, const float* __restrict__ Wo,
            const float* __restrict__ br) {
    extern __shared__ uint32_t sm[];
    int tid = threadIdx.x;
    int bm = blockIdx.x * 128;
    int lane = tid & 31, lq = lane >> 2, lr = lane & 3;
    int wid = tid >> 5, wm = wid & 3, wn = wid >> 2;
    int am = tid >> 2, aks = (tid & 3) * 4;
    int gr = bm + am;
    bool arow = gr < N_NODES;
    float c[2][8][4] = {};

    float4 ra, rb0, rb1;
    ra = arow ? __ldg((const float4*)(g_agg + (size_t)gr * HID + aks))
              : make_float4(0.f, 0.f, 0.f, 0.f);
    rb0 = __ldg((const float4*)(Wr + (size_t)am * HID + aks));
    rb1 = __ldg((const float4*)(Wr + (size_t)(am + 128) * HID + aks));

    for (int kt = 0; kt < 32; kt++) {
        int b = kt & 1;
        uint32_t* As = sm + b * STAGE;
        uint32_t* Bs = As + ASLAB;
        store_slab(As, Bs, am, aks, ra, rb0, rb1);
        float4 na = ra, nb0 = rb0, nb1 = rb1;
        if (kt < 31) {
            int k2 = kt + 1;
            int half = k2 >> 4, kc = (k2 & 15) * 16;
            const float* Asrc = half ? g_h : g_agg;
            const float* Bsrc = half ? Wo : Wr;
            na = arow ? __ldg((const float4*)(Asrc + (size_t)gr * HID + kc + aks))
                      : make_float4(0.f, 0.f, 0.f, 0.f);
            nb0 = __ldg((const float4*)(Bsrc + (size_t)am * HID + kc + aks));
            nb1 = __ldg((const float4*)(Bsrc + (size_t)(am + 128) * HID + kc + aks));
        }
        __syncthreads();
        mma_slab(As, Bs, wm, wn, lane, c);
        ra = na; rb0 = nb0; rb1 = nb1;
    }

    // epilogue: +br, store g_out, accumulate BN stats (fp32)
    float ps[8][2], pq[8][2];
#pragma unroll
    for (int nt = 0; nt < 8; nt++)
        ps[nt][0] = ps[nt][1] = pq[nt][0] = pq[nt][1] = 0.f;

#pragma unroll
    for (int mt = 0; mt < 2; mt++) {
        int row = bm + wm * 32 + mt * 16 + lq;
        bool v0 = row < N_NODES, v1 = (row + 8) < N_NODES;
#pragma unroll
        for (int nt = 0; nt < 8; nt++) {
            int col = wn * 64 + nt * 8 + lr * 2;
            float2 bb = __ldg((const float2*)(br + col));
            float o0 = c[mt][nt][0] + bb.x, o1 = c[mt][nt][1] + bb.y;
            float o2 = c[mt][nt][2] + bb.x, o3 = c[mt][nt][3] + bb.y;
            if (v0) {
                *(float2*)(g_out + (size_t)row * HID + col) = make_float2(o0, o1);
                ps[nt][0] += o0; pq[nt][0] += o0 * o0;
                ps[nt][1] += o1; pq[nt][1] += o1 * o1;
            }
            if (v1) {
                *(float2*)(g_out + (size_t)(row + 8) * HID + col) = make_float2(o2, o3);
                ps[nt][0] += o2; pq[nt][0] += o2 * o2;
                ps[nt][1] += o3; pq[nt][1] += o3 * o3;
            }
        }
    }
#pragma unroll
    for (int nt = 0; nt < 8; nt++)
#pragma unroll
        for (int u = 0; u < 2; u++) {
#pragma unroll
            for (int d = 4; d < 32; d <<= 1) {
                ps[nt][u] += __shfl_xor_sync(0xffffffffu, ps[nt][u], d);
                pq[nt][u] += __shfl_xor_sync(0xffffffffu, pq[nt][u], d);
            }
        }
    if (lq == 0) {
#pragma unroll
        for (int nt = 0; nt < 8; nt++) {
            int col = wn * 64 + nt * 8 + lr * 2;
            atomicAdd(&g_statsf[col], ps[nt][0]);
            atomicAdd(&g_statsf[col + 1], ps[nt][1]);
            atomicAdd(&g_statsf[HID + col], pq[nt][0]);
            atomicAdd(&g_statsf[HID + col + 1], pq[nt][1]);
        }
    }
}

// ---- edge GEMM1: z1 = relu(cat(h[src],h[dst]) @ W1^T + b1) ----
__global__ void __launch_bounds__(512, 1)
k_gemm_edge1(const int* __restrict__ ei, const float* __restrict__ W1,
             const float* __restrict__ b1) {
    extern __shared__ uint32_t sm[];
    int tid = threadIdx.x;
    int bm = blockIdx.x * 128;
    int lane = tid & 31, lq = lane >> 2, lr = lane & 3;
    int wid = tid >> 5, wm = wid & 3, wn = wid >> 2;
    int am = tid >> 2, aks = (tid & 3) * 4;
    int e = bm + am;
    bool val = e < N_EDGES;
    int nsrc = val ? __ldg(ei + e) : 0;
    int ndst = val ? __ldg(ei + N_EDGES + e) : 0;
    float c[2][8][4] = {};

    float4 ra, rb0, rb1;
    ra = val ? __ldg((const float4*)(g_h + (size_t)nsrc * HID + aks))
             : make_float4(0.f, 0.f, 0.f, 0.f);
    rb0 = __ldg((const float4*)(W1 + (size_t)am * 512 + aks));
    rb1 = __ldg((const float4*)(W1 + (size_t)(am + 128) * 512 + aks));

    for (int kt = 0; kt < 32; kt++) {
        int b = kt & 1;
        uint32_t* As = sm + b * STAGE;
        uint32_t* Bs = As + ASLAB;
        store_slab(As, Bs, am, aks, ra, rb0, rb1);
        float4 na = ra, nb0 = rb0, nb1 = rb1;
        if (kt < 31) {
            int k2 = kt + 1;
            int half = k2 >> 4, kc = (k2 & 15) * 16;
            int node = half ? ndst : nsrc;
            na = val ? __ldg((const float4*)(g_h + (size_t)node * HID + kc + aks))
                     : make_float4(0.f, 0.f, 0.f, 0.f);
            nb0 = __ldg((const float4*)(W1 + (size_t)am * 512 + k2 * 16 + aks));
            nb1 = __ldg((const float4*)(W1 + (size_t)(am + 128) * 512 + k2 * 16 + aks));
        }
        __syncthreads();
        mma_slab(As, Bs, wm, wn, lane, c);
        ra = na; rb0 = nb0; rb1 = nb1;
    }
#pragma unroll
    for (int mt = 0; mt < 2; mt++) {
        int row = bm + wm * 32 + mt * 16 + lq;
#pragma unroll
        for (int nt = 0; nt < 8; nt++) {
            int col = wn * 64 + nt * 8 + lr * 2;
            float2 bb = __ldg((const float2*)(b1 + col));
            if (row < N_EDGES) {
                float2 o = make_float2(fmaxf(c[mt][nt][0] + bb.x, 0.f),
                                       fmaxf(c[mt][nt][1] + bb.y, 0.f));
                *(float2*)(g_z1 + (size_t)row * HID + col) = o;
            }
            if (row + 8 < N_EDGES) {
                float2 o = make_float2(fmaxf(c[mt][nt][2] + bb.x, 0.f),
                                       fmaxf(c[mt][nt][3] + bb.y, 0.f));
                *(float2*)(g_z1 + (size_t)(row + 8) * HID + col) = o;
            }
        }
    }
}

// ---- edge GEMM2 + GEMV3 + sigmoid ----
__global__ void __launch_bounds__(512, 1)
k_gemm_edge2(const float* __restrict__ W2, const float* __restrict__ b2,
             const float* __restrict__ W3, const float* __restrict__ b3,
             float* __restrict__ dout) {
    extern __shared__ uint32_t sm[];
    __shared__ float sred[4][128];
    int tid = threadIdx.x;
    int bm = blockIdx.x * 128;
    int lane = tid & 31, lq = lane >> 2, lr = lane & 3;
    int wid = tid >> 5, wm = wid & 3, wn = wid >> 2;
    int am = tid >> 2, aks = (tid & 3) * 4;
    int e = bm + am;
    bool val = e < N_EDGES;
    float c[2][8][4] = {};

    float4 ra, rb0, rb1;
    ra = val ? __ldg((const float4*)(g_z1 + (size_t)e * HID + aks))
             : make_float4(0.f, 0.f, 0.f, 0.f);
    rb0 = __ldg((const float4*)(W2 + (size_t)am * HID + aks));
    rb1 = __ldg((const float4*)(W2 + (size_t)(am + 128) * HID + aks));

    for (int kt = 0; kt < 16; kt++) {
        int b = kt & 1;
        uint32_t* As = sm + b * STAGE;
        uint32_t* Bs = As + ASLAB;
        store_slab(As, Bs, am, aks, ra, rb0, rb1);
        float4 na = ra, nb0 = rb0, nb1 = rb1;
        if (kt < 15) {
            int kc = (kt + 1) * 16;
            na = val ? __ldg((const float4*)(g_z1 + (size_t)e * HID + kc + aks))
                     : make_float4(0.f, 0.f, 0.f, 0.f);
            nb0 = __ldg((const float4*)(W2 + (size_t)am * HID + kc + aks));
            nb1 = __ldg((const float4*)(W2 + (size_t)(am + 128) * HID + kc + aks));
        }
        __syncthreads();
        mma_slab(As, Bs, wm, wn, lane, c);
        ra = na; rb0 = nb0; rb1 = nb1;
    }

#pragma unroll
    for (int mt = 0; mt < 2; mt++) {
        float p0 = 0.f, p1 = 0.f;
#pragma unroll
        for (int nt = 0; nt < 8; nt++) {
            int col = wn * 64 + nt * 8 + lr * 2;
            float2 bb = __ldg((const float2*)(b2 + col));
            float2 ww = __ldg((const float2*)(W3 + col));
            p0 = fmaf(fmaxf(c[mt][nt][0] + bb.x, 0.f), ww.x, p0);
            p0 = fmaf(fmaxf(c[mt][nt][1] + bb.y, 0.f), ww.y, p0);
            p1 = fmaf(fmaxf(c[mt][nt][2] + bb.x, 0.f), ww.x, p1);
            p1 = fmaf(fmaxf(c[mt][nt][3] + bb.y, 0.f), ww.y, p1);
        }
        p0 += __shfl_xor_sync(0xffffffffu, p0, 1);
        p0 += __shfl_xor_sync(0xffffffffu, p0, 2);
        p1 += __shfl_xor_sync(0xffffffffu, p1, 1);
        p1 += __shfl_xor_sync(0xffffffffu, p1, 2);
        if (lr == 0) {
            sred[wn][wm * 32 + mt * 16 + lq] = p0;
            sred[wn][wm * 32 + mt * 16 + lq + 8] = p1;
        }
    }
    __syncthreads();
    if (tid < 128) {
        int gr = bm + tid;
        if (gr < N_EDGES) {
            float s = sred[0][tid] + sred[1][tid] + sred[2][tid] + sred[3][tid] + __ldg(b3);
            dout[gr] = 1.f / (1.f + expf(-s));
        }
    }
}

// ---------------------------------------------------------------- launch
extern "C" void kernel_launch(void* const* d_in, const int* in_sizes, int n_in,
                              void* d_out, int out_size) {
    const float* x     = (const float*)d_in[0];
    const int*   ei    = (const int*)  d_in[1];
    const float* Win   = (const float*)d_in[2];
    const float* Wrel  = (const float*)d_in[3];
    const float* brel  = (const float*)d_in[4];
    const float* Wroot = (const float*)d_in[5];
    const float* gamma = (const float*)d_in[6];
    const float* beta  = (const float*)d_in[7];
    const float* W1    = (const float*)d_in[8];
    const float* b1    = (const float*)d_in[9];
    const float* W2    = (const float*)d_in[10];
    const float* b2    = (const float*)d_in[11];
    const float* W3    = (const float*)d_in[12];
    const float* b3    = (const float*)d_in[13];
    float* out = (float*)d_out;

    cudaFuncSetAttribute(k_gemm_node,  cudaFuncAttributeMaxDynamicSharedMemorySize, SMEM_BYTES);
    cudaFuncSetAttribute(k_gemm_edge1, cudaFuncAttributeMaxDynamicSharedMemorySize, SMEM_BYTES);
    cudaFuncSetAttribute(k_gemm_edge2, cudaFuncAttributeMaxDynamicSharedMemorySize, SMEM_BYTES);

    k_input_fc<<<(N_NODES * HID + 255) / 256, 256>>>(x, Win);
    k_csr_count<<<(N_EDGES + 255) / 256, 256>>>(ei);
    k_csr_scan<<<1, 1024>>>();
    k_csr_fill<<<(N_EDGES + 255) / 256, 256>>>(ei);

    int node_grid = (N_NODES + 127) / 128;     // 391
    int gather_grid = (N_NODES * 32 + 255) / 256;
    for (int l = 0; l < LAYERS; l++) {
        k_gather<<<gather_grid, 256>>>();
        k_gemm_node<<<node_grid, 512, SMEM_BYTES>>>(
            Wrel + (size_t)l * HID * HID, Wroot + (size_t)l * HID * HID,
            brel + (size_t)l * HID);
        k_bn_apply<<<(N_NODES * 64 + 255) / 256, 256>>>(
            gamma + (size_t)l * HID, beta + (size_t)l * HID);
    }

    int edge_grid = (N_EDGES + 127) / 128;     // 3907
    k_gemm_edge1<<<edge_grid, 512, SMEM_BYTES>>>(ei, W1, b1);
    k_gemm_edge2<<<edge_grid, 512, SMEM_BYTES>>>(W2, b2, W3, b3, out);
}

// round 7
// speedup vs baseline: 4.0099x; 1.0864x over previous
#include <cuda_runtime.h>
#include <cuda_fp16.h>
#include <cstdint>
#include <math.h>

#define N_NODES 50000
#define N_EDGES 500000
#define HID 256
#define LAYERS 15

// ---------------------------------------------------------------- scratch
__device__ float    g_h   [(size_t)N_NODES * HID];    // fp32 residual carry
__device__ uint32_t g_hh  [(size_t)N_NODES * 128];    // h as half2
__device__ uint32_t g_aggh[(size_t)N_NODES * 128];    // agg as half2
__device__ uint32_t g_outh[(size_t)N_NODES * 128];    // pre-BN out as half2
__device__ uint32_t g_z1h [(size_t)N_EDGES * 128];    // z1 as half2
__device__ float    g_statsf[2 * HID];
// fp16 weights
__device__ uint32_t g_Wrel16 [LAYERS * 256 * 128];
__device__ uint32_t g_Wroot16[LAYERS * 256 * 128];
__device__ uint32_t g_W116[256 * 256];
__device__ uint32_t g_W216[256 * 128];
// CSR
__device__ int g_deg[N_NODES];
__device__ int g_off[N_NODES + 1];
__device__ int g_pos[N_NODES];
__device__ int g_srcs[N_EDGES];

// ---------------------------------------------------------------- helpers
__device__ __forceinline__ uint32_t pack_h2(float x, float y) {
    __half2 h = __float22half2_rn(make_float2(x, y));
    return *(uint32_t*)&h;
}
__device__ __forceinline__ float2 unpack_h2(uint32_t u) {
    return __half22float2(*(__half2*)&u);
}
__device__ __forceinline__ void mma16(float* c, uint32_t a0, uint32_t a1,
                                      uint32_t a2, uint32_t a3,
                                      uint32_t b0, uint32_t b1) {
    asm volatile(
        "mma.sync.aligned.m16n8k16.row.col.f32.f16.f16.f32 "
        "{%0,%1,%2,%3}, {%4,%5,%6,%7}, {%8,%9}, {%0,%1,%2,%3};"
        : "+f"(c[0]), "+f"(c[1]), "+f"(c[2]), "+f"(c[3])
        : "r"(a0), "r"(a1), "r"(a2), "r"(a3), "r"(b0), "r"(b1));
}

// smem (half2 units):  A2[k2 8][row 128]  B2[k2 8][col 256], strides ≡ 8 mod 32
#define ASTR2 136
#define BSTR2 264
#define ASLAB (8 * ASTR2)
#define BSLAB (8 * BSTR2)
#define STAGE (ASLAB + BSLAB)          // 3200 uints
#define SMEM_BYTES (2 * STAGE * 4)     // 25600 B

__device__ __forceinline__ void store_slab(uint32_t* As, uint32_t* Bs, int am, int k2,
                                           uint2 ra, uint2 rb0, uint2 rb1) {
    As[(k2 + 0) * ASTR2 + am] = ra.x;
    As[(k2 + 1) * ASTR2 + am] = ra.y;
    Bs[(k2 + 0) * BSTR2 + am] = rb0.x;
    Bs[(k2 + 1) * BSTR2 + am] = rb0.y;
    Bs[(k2 + 0) * BSTR2 + am + 128] = rb1.x;
    Bs[(k2 + 1) * BSTR2 + am + 128] = rb1.y;
}

__device__ __forceinline__ void mma_slab(const uint32_t* As, const uint32_t* Bs,
                                         int wm, int wn, int lane,
                                         float c[2][8][4]) {
    int g = lane >> 2, t = lane & 3;
    uint32_t b0[8], b1[8];
#pragma unroll
    for (int nt = 0; nt < 8; nt++) {
        int C = wn * 64 + nt * 8 + g;
        b0[nt] = Bs[t * BSTR2 + C];
        b1[nt] = Bs[(t + 4) * BSTR2 + C];
    }
#pragma unroll
    for (int mt = 0; mt < 2; mt++) {
        int R = wm * 32 + mt * 16 + g;
        uint32_t a0 = As[t * ASTR2 + R];
        uint32_t a1 = As[t * ASTR2 + R + 8];
        uint32_t a2 = As[(t + 4) * ASTR2 + R];
        uint32_t a3 = As[(t + 4) * ASTR2 + R + 8];
#pragma unroll
        for (int nt = 0; nt < 8; nt++)
            mma16(c[mt][nt], a0, a1, a2, a3, b0[nt], b1[nt]);
    }
}

// ---------------------------------------------------------------- small kernels
__global__ void k_cvt_weights(const float* __restrict__ Wrel,
                              const float* __restrict__ Wroot,
                              const float* __restrict__ W1,
                              const float* __restrict__ W2) {
    const int NREL = LAYERS * 256 * 128;       // 491520
    const int NW1 = 256 * 256;                 // 65536
    const int NW2 = 256 * 128;                 // 32768
    int i = blockIdx.x * blockDim.x + threadIdx.x;
    if (i < NREL) {
        g_Wrel16[i] = pack_h2(Wrel[2 * i], Wrel[2 * i + 1]);
        g_Wroot16[i] = pack_h2(Wroot[2 * i], Wroot[2 * i + 1]);
    } else {
        int j = i - NREL;
        if (j < NW1) g_W116[j] = pack_h2(W1[2 * j], W1[2 * j + 1]);
        else if (j - NW1 < NW2) {
            int k = j - NW1;
            g_W216[k] = pack_h2(W2[2 * k], W2[2 * k + 1]);
        }
    }
}

__global__ void k_input_fc(const float* __restrict__ x, const float* __restrict__ Win) {
    int idx = blockIdx.x * blockDim.x + threadIdx.x;   // half2 units
    if (idx < 2 * HID) g_statsf[idx] = 0.f;
    if (idx < N_NODES) g_deg[idx] = 0;
    if (idx >= N_NODES * 128) return;
    int node = idx >> 7, c0 = (idx & 127) * 2;
    float x0 = x[node * 2], x1 = x[node * 2 + 1];
    float h0 = x0 * Win[c0 * 2] + x1 * Win[c0 * 2 + 1];
    float h1 = x0 * Win[c0 * 2 + 2] + x1 * Win[c0 * 2 + 3];
    ((float2*)g_h)[idx] = make_float2(h0, h1);
    g_hh[idx] = pack_h2(h0, h1);
}

__global__ void k_csr_count(const int* __restrict__ ei) {
    int e = blockIdx.x * blockDim.x + threadIdx.x;
    if (e >= N_EDGES) return;
    atomicAdd(&g_deg[__ldg(ei + N_EDGES + e)], 1);
}

__global__ void k_csr_scan() {     // 1 block, 1024 threads
    __shared__ int wsum[32];
    __shared__ int s_carry;
    int tid = threadIdx.x, lane = tid & 31, wid = tid >> 5;
    if (tid == 0) s_carry = 0;
    __syncthreads();
    for (int base = 0; base < N_NODES; base += 1024) {
        int i = base + tid;
        int v = (i < N_NODES) ? g_deg[i] : 0;
        int x = v;
#pragma unroll
        for (int d = 1; d < 32; d <<= 1) {
            int y = __shfl_up_sync(0xffffffffu, x, d);
            if (lane >= d) x += y;
        }
        if (lane == 31) wsum[wid] = x;
        __syncthreads();
        if (wid == 0) {
            int w = wsum[lane];
#pragma unroll
            for (int d = 1; d < 32; d <<= 1) {
                int y = __shfl_up_sync(0xffffffffu, w, d);
                if (lane >= d) w += y;
            }
            wsum[lane] = w;
        }
        __syncthreads();
        int carry = s_carry;
        int incl = x + (wid > 0 ? wsum[wid - 1] : 0);
        if (i < N_NODES) {
            int excl = carry + incl - v;
            g_off[i] = excl;
            g_pos[i] = excl;
        }
        __syncthreads();
        if (tid == 0) s_carry = carry + wsum[31];
        __syncthreads();
    }
    if (threadIdx.x == 0) g_off[N_NODES] = s_carry;
}

__global__ void k_csr_fill(const int* __restrict__ ei) {
    int e = blockIdx.x * blockDim.x + threadIdx.x;
    if (e >= N_EDGES) return;
    int d = __ldg(ei + N_EDGES + e);
    int p = atomicAdd(&g_pos[d], 1);
    g_srcs[p] = __ldg(ei + e);
}

// ---- gather: aggh[n] = sum hh[src] (fp32 accum); warp/node ----
__global__ void k_gather() {
    if (blockIdx.x == 0 && threadIdx.x < HID) {
        g_statsf[threadIdx.x] = 0.f;
        g_statsf[HID + threadIdx.x] = 0.f;
    }
    int gw = (blockIdx.x * blockDim.x + threadIdx.x) >> 5;
    int lane = threadIdx.x & 31;
    if (gw >= N_NODES) return;
    int beg = g_off[gw], end = g_off[gw + 1];
    float acc[8] = {};
    const uint4* hp = (const uint4*)g_hh;   // 32 uint4 per node row
    int i = beg;
    for (; i + 1 < end; i += 2) {
        int s0 = __ldg(&g_srcs[i]);
        int s1 = __ldg(&g_srcs[i + 1]);
        uint4 v0 = __ldg(hp + (size_t)s0 * 32 + lane);
        uint4 v1 = __ldg(hp + (size_t)s1 * 32 + lane);
        float2 f;
        f = unpack_h2(v0.x); acc[0] += f.x; acc[1] += f.y;
        f = unpack_h2(v0.y); acc[2] += f.x; acc[3] += f.y;
        f = unpack_h2(v0.z); acc[4] += f.x; acc[5] += f.y;
        f = unpack_h2(v0.w); acc[6] += f.x; acc[7] += f.y;
        f = unpack_h2(v1.x); acc[0] += f.x; acc[1] += f.y;
        f = unpack_h2(v1.y); acc[2] += f.x; acc[3] += f.y;
        f = unpack_h2(v1.z); acc[4] += f.x; acc[5] += f.y;
        f = unpack_h2(v1.w); acc[6] += f.x; acc[7] += f.y;
    }
    if (i < end) {
        int s0 = __ldg(&g_srcs[i]);
        uint4 v0 = __ldg(hp + (size_t)s0 * 32 + lane);
        float2 f;
        f = unpack_h2(v0.x); acc[0] += f.x; acc[1] += f.y;
        f = unpack_h2(v0.y); acc[2] += f.x; acc[3] += f.y;
        f = unpack_h2(v0.z); acc[4] += f.x; acc[5] += f.y;
        f = unpack_h2(v0.w); acc[6] += f.x; acc[7] += f.y;
    }
    uint4 o;
    o.x = pack_h2(acc[0], acc[1]);
    o.y = pack_h2(acc[2], acc[3]);
    o.z = pack_h2(acc[4], acc[5]);
    o.w = pack_h2(acc[6], acc[7]);
    ((uint4*)g_aggh)[(size_t)gw * 32 + lane] = o;
}

// ---- BN finalize + apply fused: h += relu(out*sc + sh); refresh hh ----
__global__ void k_bn_apply(const float* __restrict__ gm, const float* __restrict__ bt) {
    __shared__ float ssc[HID], ssh[HID];
    int tid = threadIdx.x;
    if (tid < HID) {
        float mean = g_statsf[tid] * (1.f / N_NODES);
        float var  = g_statsf[HID + tid] * (1.f / N_NODES) - mean * mean;
        float rstd = rsqrtf(var + 1e-5f);
        float sc = rstd * __ldg(gm + tid);
        ssc[tid] = sc;
        ssh[tid] = __ldg(bt + tid) - mean * sc;
    }
    __syncthreads();
    int idx = blockIdx.x * blockDim.x + tid;   // half2 units
    if (idx >= N_NODES * 128) return;
    int c0 = (idx & 127) * 2;
    float2 o = unpack_h2(g_outh[idx]);
    float2 hv = ((float2*)g_h)[idx];
    hv.x += fmaxf(fmaf(o.x, ssc[c0], ssh[c0]), 0.f);
    hv.y += fmaxf(fmaf(o.y, ssc[c0 + 1], ssh[c0 + 1]), 0.f);
    ((float2*)g_h)[idx] = hv;
    g_hh[idx] = pack_h2(hv.x, hv.y);
}

// =================================================================
// fp16 mma.sync GEMM: 512 thr, 16 warps (4m x 4n), BM=128 BN=256 BK=16
// all inputs pre-converted fp16 -> mainloop is pure uint copies
// =================================================================

// ---- node GEMM: out = agg@Wr^T + h@Wo^T + br, fused BN stats ----
__global__ void __launch_bounds__(512, 1)
k_gemm_node(int layer, const float* __restrict__ br) {
    extern __shared__ uint32_t sm[];
    int tid = threadIdx.x;
    int bm = blockIdx.x * 128;
    int lane = tid & 31, lq = lane >> 2, lr = lane & 3;
    int wid = tid >> 5, wm = wid & 3, wn = wid >> 2;
    int am = tid >> 2, aks = (tid & 3) * 4;    // cols aks..aks+3
    int k2 = aks >> 1;
    int gr = bm + am;
    bool arow = gr < N_NODES;
    const uint32_t* Wr = g_Wrel16 + (size_t)layer * 256 * 128;
    const uint32_t* Wo = g_Wroot16 + (size_t)layer * 256 * 128;
    float c[2][8][4] = {};

    uint2 ra, rb0, rb1;
    ra = arow ? __ldg((const uint2*)(g_aggh + (size_t)gr * 128) + k2 / 2)
              : make_uint2(0u, 0u);
    rb0 = __ldg((const uint2*)(Wr + (size_t)am * 128) + k2 / 2);
    rb1 = __ldg((const uint2*)(Wr + (size_t)(am + 128) * 128) + k2 / 2);

    for (int kt = 0; kt < 32; kt++) {
        int b = kt & 1;
        uint32_t* As = sm + b * STAGE;
        uint32_t* Bs = As + ASLAB;
        store_slab(As, Bs, am, k2, ra, rb0, rb1);
        uint2 na = ra, nb0 = rb0, nb1 = rb1;
        if (kt < 31) {
            int kk = kt + 1;
            int half = kk >> 4;
            int kc2 = ((kk & 15) * 16 + aks) >> 2;   // uint2 index within row
            const uint32_t* Asrc = half ? g_hh : g_aggh;
            const uint32_t* Bsrc = half ? Wo : Wr;
            na = arow ? __ldg((const uint2*)(Asrc + (size_t)gr * 128) + kc2)
                      : make_uint2(0u, 0u);
            nb0 = __ldg((const uint2*)(Bsrc + (size_t)am * 128) + kc2);
            nb1 = __ldg((const uint2*)(Bsrc + (size_t)(am + 128) * 128) + kc2);
        }
        __syncthreads();
        mma_slab(As, Bs, wm, wn, lane, c);
        ra = na; rb0 = nb0; rb1 = nb1;
    }

    // epilogue: +br, store g_outh (half2), accumulate BN stats (fp32)
    float ps[8][2], pq[8][2];
#pragma unroll
    for (int nt = 0; nt < 8; nt++)
        ps[nt][0] = ps[nt][1] = pq[nt][0] = pq[nt][1] = 0.f;

#pragma unroll
    for (int mt = 0; mt < 2; mt++) {
        int row = bm + wm * 32 + mt * 16 + lq;
        bool v0 = row < N_NODES, v1 = (row + 8) < N_NODES;
#pragma unroll
        for (int nt = 0; nt < 8; nt++) {
            int col = wn * 64 + nt * 8 + lr * 2;
            float2 bb = __ldg((const float2*)(br + col));
            float o0 = c[mt][nt][0] + bb.x, o1 = c[mt][nt][1] + bb.y;
            float o2 = c[mt][nt][2] + bb.x, o3 = c[mt][nt][3] + bb.y;
            if (v0) {
                g_outh[(size_t)row * 128 + (col >> 1)] = pack_h2(o0, o1);
                ps[nt][0] += o0; pq[nt][0] += o0 * o0;
                ps[nt][1] += o1; pq[nt][1] += o1 * o1;
            }
            if (v1) {
                g_outh[(size_t)(row + 8) * 128 + (col >> 1)] = pack_h2(o2, o3);
                ps[nt][0] += o2; pq[nt][0] += o2 * o2;
                ps[nt][1] += o3; pq[nt][1] += o3 * o3;
            }
        }
    }
#pragma unroll
    for (int nt = 0; nt < 8; nt++)
#pragma unroll
        for (int u = 0; u < 2; u++) {
#pragma unroll
            for (int d = 4; d < 32; d <<= 1) {
                ps[nt][u] += __shfl_xor_sync(0xffffffffu, ps[nt][u], d);
                pq[nt][u] += __shfl_xor_sync(0xffffffffu, pq[nt][u], d);
            }
        }
    if (lq == 0) {
#pragma unroll
        for (int nt = 0; nt < 8; nt++) {
            int col = wn * 64 + nt * 8 + lr * 2;
            atomicAdd(&g_statsf[col], ps[nt][0]);
            atomicAdd(&g_statsf[col + 1], ps[nt][1]);
            atomicAdd(&g_statsf[HID + col], pq[nt][0]);
            atomicAdd(&g_statsf[HID + col + 1], pq[nt][1]);
        }
    }
}

// ---- edge GEMM1: z1 = relu(cat(hh[src],hh[dst]) @ W1^T + b1) -> z1h ----
__global__ void __launch_bounds__(512, 1)
k_gemm_edge1(const int* __restrict__ ei, const float* __restrict__ b1) {
    extern __shared__ uint32_t sm[];
    int tid = threadIdx.x;
    int bm = blockIdx.x * 128;
    int lane = tid & 31, lq = lane >> 2, lr = lane & 3;
    int wid = tid >> 5, wm = wid & 3, wn = wid >> 2;
    int am = tid >> 2, aks = (tid & 3) * 4;
    int k2 = aks >> 1;
    int e = bm + am;
    bool val = e < N_EDGES;
    int nsrc = val ? __ldg(ei + e) : 0;
    int ndst = val ? __ldg(ei + N_EDGES + e) : 0;
    float c[2][8][4] = {};

    uint2 ra, rb0, rb1;
    ra = val ? __ldg((const uint2*)(g_hh + (size_t)nsrc * 128) + k2 / 2)
             : make_uint2(0u, 0u);
    rb0 = __ldg((const uint2*)(g_W116 + (size_t)am * 256) + k2 / 2);
    rb1 = __ldg((const uint2*)(g_W116 + (size_t)(am + 128) * 256) + k2 / 2);

    for (int kt = 0; kt < 32; kt++) {
        int b = kt & 1;
        uint32_t* As = sm + b * STAGE;
        uint32_t* Bs = As + ASLAB;
        store_slab(As, Bs, am, k2, ra, rb0, rb1);
        uint2 na = ra, nb0 = rb0, nb1 = rb1;
        if (kt < 31) {
            int kk = kt + 1;
            int half = kk >> 4;
            int node = half ? ndst : nsrc;
            int kc2a = ((kk & 15) * 16 + aks) >> 2;
            int kc2b = (kk * 16 + aks) >> 2;
            na = val ? __ldg((const uint2*)(g_hh + (size_t)node * 128) + kc2a)
                     : make_uint2(0u, 0u);
            nb0 = __ldg((const uint2*)(g_W116 + (size_t)am * 256) + kc2b);
            nb1 = __ldg((const uint2*)(g_W116 + (size_t)(am + 128) * 256) + kc2b);
        }
        __syncthreads();
        mma_slab(As, Bs, wm, wn, lane, c);
        ra = na; rb0 = nb0; rb1 = nb1;
    }
#pragma unroll
    for (int mt = 0; mt < 2; mt++) {
        int row = bm + wm * 32 + mt * 16 + lq;
#pragma unroll
        for (int nt = 0; nt < 8; nt++) {
            int col = wn * 64 + nt * 8 + lr * 2;
            float2 bb = __ldg((const float2*)(b1 + col));
            if (row < N_EDGES)
                g_z1h[(size_t)row * 128 + (col >> 1)] =
                    pack_h2(fmaxf(c[mt][nt][0] + bb.x, 0.f),
                            fmaxf(c[mt][nt][1] + bb.y, 0.f));
            if (row + 8 < N_EDGES)
                g_z1h[(size_t)(row + 8) * 128 + (col >> 1)] =
                    pack_h2(fmaxf(c[mt][nt][2] + bb.x, 0.f),
                            fmaxf(c[mt][nt][3] + bb.y, 0.f));
        }
    }
}

// ---- edge GEMM2 + GEMV3 + sigmoid ----
__global__ void __launch_bounds__(512, 1)
k_gemm_edge2(const float* __restrict__ b2, const float* __restrict__ W3,
             const float* __restrict__ b3, float* __restrict__ dout) {
    extern __shared__ uint32_t sm[];
    __shared__ float sred[4][128];
    int tid = threadIdx.x;
    int bm = blockIdx.x * 128;
    int lane = tid & 31, lq = lane >> 2, lr = lane & 3;
    int wid = tid >> 5, wm = wid & 3, wn = wid >> 2;
    int am = tid >> 2, aks = (tid & 3) * 4;
    int k2 = aks >> 1;
    int e = bm + am;
    bool val = e < N_EDGES;
    float c[2][8][4] = {};

    uint2 ra, rb0, rb1;
    ra = val ? __ldg((const uint2*)(g_z1h + (size_t)e * 128) + k2 / 2)
             : make_uint2(0u, 0u);
    rb0 = __ldg((const uint2*)(g_W216 + (size_t)am * 128) + k2 / 2);
    rb1 = __ldg((const uint2*)(g_W216 + (size_t)(am + 128) * 128) + k2 / 2);

    for (int kt = 0; kt < 16; kt++) {
        int b = kt & 1;
        uint32_t* As = sm + b * STAGE;
        uint32_t* Bs = As + ASLAB;
        store_slab(As, Bs, am, k2, ra, rb0, rb1);
        uint2 na = ra, nb0 = rb0, nb1 = rb1;
        if (kt < 15) {
            int kc2 = ((kt + 1) * 16 + aks) >> 2;
            na = val ? __ldg((const uint2*)(g_z1h + (size_t)e * 128) + kc2)
                     : make_uint2(0u, 0u);
            nb0 = __ldg((const uint2*)(g_W216 + (size_t)am * 128) + kc2);
            nb1 = __ldg((const uint2*)(g_W216 + (size_t)(am + 128) * 128) + kc2);
        }
        __syncthreads();
        mma_slab(As, Bs, wm, wn, lane, c);
        ra = na; rb0 = nb0; rb1 = nb1;
    }

#pragma unroll
    for (int mt = 0; mt < 2; mt++) {
        float p0 = 0.f, p1 = 0.f;
#pragma unroll
        for (int nt = 0; nt < 8; nt++) {
            int col = wn * 64 + nt * 8 + lr * 2;
            float2 bb = __ldg((const float2*)(b2 + col));
            float2 ww = __ldg((const float2*)(W3 + col));
            p0 = fmaf(fmaxf(c[mt][nt][0] + bb.x, 0.f), ww.x, p0);
            p0 = fmaf(fmaxf(c[mt][nt][1] + bb.y, 0.f), ww.y, p0);
            p1 = fmaf(fmaxf(c[mt][nt][2] + bb.x, 0.f), ww.x, p1);
            p1 = fmaf(fmaxf(c[mt][nt][3] + bb.y, 0.f), ww.y, p1);
        }
        p0 += __shfl_xor_sync(0xffffffffu, p0, 1);
        p0 += __shfl_xor_sync(0xffffffffu, p0, 2);
        p1 += __shfl_xor_sync(0xffffffffu, p1, 1);
        p1 += __shfl_xor_sync(0xffffffffu, p1, 2);
        if (lr == 0) {
            sred[wn][wm * 32 + mt * 16 + lq] = p0;
            sred[wn][wm * 32 + mt * 16 + lq + 8] = p1;
        }
    }
    __syncthreads();
    if (tid < 128) {
        int gr = bm + tid;
        if (gr < N_EDGES) {
            float s = sred[0][tid] + sred[1][tid] + sred[2][tid] + sred[3][tid] + __ldg(b3);
            dout[gr] = 1.f / (1.f + expf(-s));
        }
    }
}

// ---------------------------------------------------------------- launch
extern "C" void kernel_launch(void* const* d_in, const int* in_sizes, int n_in,
                              void* d_out, int out_size) {
    const float* x     = (const float*)d_in[0];
    const int*   ei    = (const int*)  d_in[1];
    const float* Win   = (const float*)d_in[2];
    const float* Wrel  = (const float*)d_in[3];
    const float* brel  = (const float*)d_in[4];
    const float* Wroot = (const float*)d_in[5];
    const float* gamma = (const float*)d_in[6];
    const float* beta  = (const float*)d_in[7];
    const float* W1    = (const float*)d_in[8];
    const float* b1    = (const float*)d_in[9];
    const float* W2    = (const float*)d_in[10];
    const float* b2    = (const float*)d_in[11];
    const float* W3    = (const float*)d_in[12];
    const float* b3    = (const float*)d_in[13];
    float* out = (float*)d_out;

    cudaFuncSetAttribute(k_gemm_node,  cudaFuncAttributeMaxDynamicSharedMemorySize, SMEM_BYTES);
    cudaFuncSetAttribute(k_gemm_edge1, cudaFuncAttributeMaxDynamicSharedMemorySize, SMEM_BYTES);
    cudaFuncSetAttribute(k_gemm_edge2, cudaFuncAttributeMaxDynamicSharedMemorySize, SMEM_BYTES);

    int ncvt = LAYERS * 256 * 128 + 256 * 256 + 256 * 128;
    k_cvt_weights<<<(ncvt + 255) / 256, 256>>>(Wrel, Wroot, W1, W2);
    k_input_fc<<<(N_NODES * 128 + 255) / 256, 256>>>(x, Win);
    k_csr_count<<<(N_EDGES + 255) / 256, 256>>>(ei);
    k_csr_scan<<<1, 1024>>>();
    k_csr_fill<<<(N_EDGES + 255) / 256, 256>>>(ei);

    int node_grid = (N_NODES + 127) / 128;     // 391
    int gather_grid = (N_NODES * 32 + 255) / 256;
    for (int l = 0; l < LAYERS; l++) {
        k_gather<<<gather_grid, 256>>>();
        k_gemm_node<<<node_grid, 512, SMEM_BYTES>>>(l, brel + (size_t)l * HID);
        k_bn_apply<<<(N_NODES * 128 + 255) / 256, 256>>>(
            gamma + (size_t)l * HID, beta + (size_t)l * HID);
    }

    int edge_grid = (N_EDGES + 127) / 128;     // 3907
    k_gemm_edge1<<<edge_grid, 512, SMEM_BYTES>>>(ei, b1);
    k_gemm_edge2<<<edge_grid, 512, SMEM_BYTES>>>(b2, W3, b3, out);
}

// round 8
// speedup vs baseline: 4.0335x; 1.0059x over previous
#include <cuda_runtime.h>
#include <cuda_fp16.h>
#include <cstdint>
#include <math.h>

#define N_NODES 50000
#define N_EDGES 500000
#define HID 256
#define LAYERS 15

// ---------------------------------------------------------------- scratch
__device__ float    g_h   [(size_t)N_NODES * HID];    // fp32 residual carry
__device__ uint32_t g_hh  [(size_t)N_NODES * 128];    // h as half2
__device__ uint32_t g_aggh[(size_t)N_NODES * 128];    // agg as half2
__device__ uint32_t g_outh[(size_t)N_NODES * 128];    // pre-BN out as half2
__device__ float    g_statsf[2 * HID];
// fp16 weights
__device__ uint32_t g_Wrel16 [LAYERS * 256 * 128];
__device__ uint32_t g_Wroot16[LAYERS * 256 * 128];
__device__ uint32_t g_W116[256 * 256];
__device__ uint32_t g_W216[256 * 128];
// CSR
__device__ int g_deg[N_NODES];
__device__ int g_off[N_NODES + 1];
__device__ int g_pos[N_NODES];
__device__ int g_srcs[N_EDGES];

// ---------------------------------------------------------------- helpers
__device__ __forceinline__ uint32_t pack_h2(float x, float y) {
    __half2 h = __float22half2_rn(make_float2(x, y));
    return *(uint32_t*)&h;
}
__device__ __forceinline__ float2 unpack_h2(uint32_t u) {
    return __half22float2(*(__half2*)&u);
}
__device__ __forceinline__ void mma16(float* c, uint32_t a0, uint32_t a1,
                                      uint32_t a2, uint32_t a3,
                                      uint32_t b0, uint32_t b1) {
    asm volatile(
        "mma.sync.aligned.m16n8k16.row.col.f32.f16.f16.f32 "
        "{%0,%1,%2,%3}, {%4,%5,%6,%7}, {%8,%9}, {%0,%1,%2,%3};"
        : "+f"(c[0]), "+f"(c[1]), "+f"(c[2]), "+f"(c[3])
        : "r"(a0), "r"(a1), "r"(a2), "r"(a3), "r"(b0), "r"(b1));
}

// smem (half2 units):  A2[k2 8][row 128]  B2[k2 8][col 256], strides ≡ 8 mod 32
#define ASTR2 136
#define BSTR2 264
#define ASLAB (8 * ASTR2)              // 1088
#define BSLAB (8 * BSTR2)              // 2112
#define STAGE (ASLAB + BSLAB)          // 3200 uints
#define SMEM_BYTES (2 * STAGE * 4)     // 25600 B
// fused edge kernel: z1 tile region (16 slabs x 1088) + double buffers
#define Z1U (16 * ASLAB)               // 17408 uints
#define EDGE_SMEM ((Z1U + 2 * STAGE) * 4)   // 95232 B

__device__ __forceinline__ void store_slab(uint32_t* As, uint32_t* Bs, int am, int k2,
                                           uint2 ra, uint2 rb0, uint2 rb1) {
    As[(k2 + 0) * ASTR2 + am] = ra.x;
    As[(k2 + 1) * ASTR2 + am] = ra.y;
    Bs[(k2 + 0) * BSTR2 + am] = rb0.x;
    Bs[(k2 + 1) * BSTR2 + am] = rb0.y;
    Bs[(k2 + 0) * BSTR2 + am + 128] = rb1.x;
    Bs[(k2 + 1) * BSTR2 + am + 128] = rb1.y;
}
__device__ __forceinline__ void store_slab_b(uint32_t* Bs, int am, int k2,
                                             uint2 rb0, uint2 rb1) {
    Bs[(k2 + 0) * BSTR2 + am] = rb0.x;
    Bs[(k2 + 1) * BSTR2 + am] = rb0.y;
    Bs[(k2 + 0) * BSTR2 + am + 128] = rb1.x;
    Bs[(k2 + 1) * BSTR2 + am + 128] = rb1.y;
}

__device__ __forceinline__ void mma_slab(const uint32_t* As, const uint32_t* Bs,
                                         int wm, int wn, int lane,
                                         float c[2][8][4]) {
    int g = lane >> 2, t = lane & 3;
    uint32_t b0[8], b1[8];
#pragma unroll
    for (int nt = 0; nt < 8; nt++) {
        int C = wn * 64 + nt * 8 + g;
        b0[nt] = Bs[t * BSTR2 + C];
        b1[nt] = Bs[(t + 4) * BSTR2 + C];
    }
#pragma unroll
    for (int mt = 0; mt < 2; mt++) {
        int R = wm * 32 + mt * 16 + g;
        uint32_t a0 = As[t * ASTR2 + R];
        uint32_t a1 = As[t * ASTR2 + R + 8];
        uint32_t a2 = As[(t + 4) * ASTR2 + R];
        uint32_t a3 = As[(t + 4) * ASTR2 + R + 8];
#pragma unroll
        for (int nt = 0; nt < 8; nt++)
            mma16(c[mt][nt], a0, a1, a2, a3, b0[nt], b1[nt]);
    }
}

// ---------------------------------------------------------------- small kernels
__global__ void k_cvt_weights(const float* __restrict__ Wrel,
                              const float* __restrict__ Wroot,
                              const float* __restrict__ W1,
                              const float* __restrict__ W2) {
    const int NREL = LAYERS * 256 * 128;
    const int NW1 = 256 * 256;
    const int NW2 = 256 * 128;
    int i = blockIdx.x * blockDim.x + threadIdx.x;
    if (i < NREL) {
        g_Wrel16[i] = pack_h2(Wrel[2 * i], Wrel[2 * i + 1]);
        g_Wroot16[i] = pack_h2(Wroot[2 * i], Wroot[2 * i + 1]);
    } else {
        int j = i - NREL;
        if (j < NW1) g_W116[j] = pack_h2(W1[2 * j], W1[2 * j + 1]);
        else if (j - NW1 < NW2) {
            int k = j - NW1;
            g_W216[k] = pack_h2(W2[2 * k], W2[2 * k + 1]);
        }
    }
}

__global__ void k_input_fc(const float* __restrict__ x, const float* __restrict__ Win) {
    int idx = blockIdx.x * blockDim.x + threadIdx.x;   // half2 units
    if (idx < 2 * HID) g_statsf[idx] = 0.f;
    if (idx < N_NODES) g_deg[idx] = 0;
    if (idx >= N_NODES * 128) return;
    int node = idx >> 7, c0 = (idx & 127) * 2;
    float x0 = x[node * 2], x1 = x[node * 2 + 1];
    float h0 = x0 * Win[c0 * 2] + x1 * Win[c0 * 2 + 1];
    float h1 = x0 * Win[c0 * 2 + 2] + x1 * Win[c0 * 2 + 3];
    ((float2*)g_h)[idx] = make_float2(h0, h1);
    g_hh[idx] = pack_h2(h0, h1);
}

__global__ void k_csr_count(const int* __restrict__ ei) {
    int e = blockIdx.x * blockDim.x + threadIdx.x;
    if (e >= N_EDGES) return;
    atomicAdd(&g_deg[__ldg(ei + N_EDGES + e)], 1);
}

__global__ void k_csr_scan() {     // 1 block, 1024 threads
    __shared__ int wsum[32];
    __shared__ int s_carry;
    int tid = threadIdx.x, lane = tid & 31, wid = tid >> 5;
    if (tid == 0) s_carry = 0;
    __syncthreads();
    for (int base = 0; base < N_NODES; base += 1024) {
        int i = base + tid;
        int v = (i < N_NODES) ? g_deg[i] : 0;
        int x = v;
#pragma unroll
        for (int d = 1; d < 32; d <<= 1) {
            int y = __shfl_up_sync(0xffffffffu, x, d);
            if (lane >= d) x += y;
        }
        if (lane == 31) wsum[wid] = x;
        __syncthreads();
        if (wid == 0) {
            int w = wsum[lane];
#pragma unroll
            for (int d = 1; d < 32; d <<= 1) {
                int y = __shfl_up_sync(0xffffffffu, w, d);
                if (lane >= d) w += y;
            }
            wsum[lane] = w;
        }
        __syncthreads();
        int carry = s_carry;
        int incl = x + (wid > 0 ? wsum[wid - 1] : 0);
        if (i < N_NODES) {
            int excl = carry + incl - v;
            g_off[i] = excl;
            g_pos[i] = excl;
        }
        __syncthreads();
        if (tid == 0) s_carry = carry + wsum[31];
        __syncthreads();
    }
    if (threadIdx.x == 0) g_off[N_NODES] = s_carry;
}

__global__ void k_csr_fill(const int* __restrict__ ei) {
    int e = blockIdx.x * blockDim.x + threadIdx.x;
    if (e >= N_EDGES) return;
    int d = __ldg(ei + N_EDGES + e);
    int p = atomicAdd(&g_pos[d], 1);
    g_srcs[p] = __ldg(ei + e);
}

// ---- gather: aggh[n] = sum hh[src] (fp32 accum); warp/node ----
__global__ void k_gather() {
    if (blockIdx.x == 0 && threadIdx.x < HID) {
        g_statsf[threadIdx.x] = 0.f;
        g_statsf[HID + threadIdx.x] = 0.f;
    }
    int gw = (blockIdx.x * blockDim.x + threadIdx.x) >> 5;
    int lane = threadIdx.x & 31;
    if (gw >= N_NODES) return;
    int beg = g_off[gw], end = g_off[gw + 1];
    float acc[8] = {};
    const uint4* hp = (const uint4*)g_hh;
    int i = beg;
    for (; i + 1 < end; i += 2) {
        int s0 = __ldg(&g_srcs[i]);
        int s1 = __ldg(&g_srcs[i + 1]);
        uint4 v0 = __ldg(hp + (size_t)s0 * 32 + lane);
        uint4 v1 = __ldg(hp + (size_t)s1 * 32 + lane);
        float2 f;
        f = unpack_h2(v0.x); acc[0] += f.x; acc[1] += f.y;
        f = unpack_h2(v0.y); acc[2] += f.x; acc[3] += f.y;
        f = unpack_h2(v0.z); acc[4] += f.x; acc[5] += f.y;
        f = unpack_h2(v0.w); acc[6] += f.x; acc[7] += f.y;
        f = unpack_h2(v1.x); acc[0] += f.x; acc[1] += f.y;
        f = unpack_h2(v1.y); acc[2] += f.x; acc[3] += f.y;
        f = unpack_h2(v1.z); acc[4] += f.x; acc[5] += f.y;
        f = unpack_h2(v1.w); acc[6] += f.x; acc[7] += f.y;
    }
    if (i < end) {
        int s0 = __ldg(&g_srcs[i]);
        uint4 v0 = __ldg(hp + (size_t)s0 * 32 + lane);
        float2 f;
        f = unpack_h2(v0.x); acc[0] += f.x; acc[1] += f.y;
        f = unpack_h2(v0.y); acc[2] += f.x; acc[3] += f.y;
        f = unpack_h2(v0.z); acc[4] += f.x; acc[5] += f.y;
        f = unpack_h2(v0.w); acc[6] += f.x; acc[7] += f.y;
    }
    uint4 o;
    o.x = pack_h2(acc[0], acc[1]);
    o.y = pack_h2(acc[2], acc[3]);
    o.z = pack_h2(acc[4], acc[5]);
    o.w = pack_h2(acc[6], acc[7]);
    ((uint4*)g_aggh)[(size_t)gw * 32 + lane] = o;
}

// ---- BN finalize + apply fused ----
__global__ void k_bn_apply(const float* __restrict__ gm, const float* __restrict__ bt) {
    __shared__ float ssc[HID], ssh[HID];
    int tid = threadIdx.x;
    if (tid < HID) {
        float mean = g_statsf[tid] * (1.f / N_NODES);
        float var  = g_statsf[HID + tid] * (1.f / N_NODES) - mean * mean;
        float rstd = rsqrtf(var + 1e-5f);
        float sc = rstd * __ldg(gm + tid);
        ssc[tid] = sc;
        ssh[tid] = __ldg(bt + tid) - mean * sc;
    }
    __syncthreads();
    int idx = blockIdx.x * blockDim.x + tid;
    if (idx >= N_NODES * 128) return;
    int c0 = (idx & 127) * 2;
    float2 o = unpack_h2(g_outh[idx]);
    float2 hv = ((float2*)g_h)[idx];
    hv.x += fmaxf(fmaf(o.x, ssc[c0], ssh[c0]), 0.f);
    hv.y += fmaxf(fmaf(o.y, ssc[c0 + 1], ssh[c0 + 1]), 0.f);
    ((float2*)g_h)[idx] = hv;
    g_hh[idx] = pack_h2(hv.x, hv.y);
}

// ---- node GEMM: out = agg@Wr^T + h@Wo^T + br, fused BN stats ----
__global__ void __launch_bounds__(512, 1)
k_gemm_node(int layer, const float* __restrict__ br) {
    extern __shared__ uint32_t sm[];
    int tid = threadIdx.x;
    int bm = blockIdx.x * 128;
    int lane = tid & 31, lq = lane >> 2, lr = lane & 3;
    int wid = tid >> 5, wm = wid & 3, wn = wid >> 2;
    int am = tid >> 2, aks = (tid & 3) * 4;
    int k2 = aks >> 1;
    int gr = bm + am;
    bool arow = gr < N_NODES;
    const uint32_t* Wr = g_Wrel16 + (size_t)layer * 256 * 128;
    const uint32_t* Wo = g_Wroot16 + (size_t)layer * 256 * 128;
    float c[2][8][4] = {};

    uint2 ra, rb0, rb1;
    ra = arow ? __ldg((const uint2*)(g_aggh + (size_t)gr * 128) + k2 / 2)
              : make_uint2(0u, 0u);
    rb0 = __ldg((const uint2*)(Wr + (size_t)am * 128) + k2 / 2);
    rb1 = __ldg((const uint2*)(Wr + (size_t)(am + 128) * 128) + k2 / 2);

    for (int kt = 0; kt < 32; kt++) {
        int b = kt & 1;
        uint32_t* As = sm + b * STAGE;
        uint32_t* Bs = As + ASLAB;
        store_slab(As, Bs, am, k2, ra, rb0, rb1);
        uint2 na = ra, nb0 = rb0, nb1 = rb1;
        if (kt < 31) {
            int kk = kt + 1;
            int half = kk >> 4;
            int kc2 = ((kk & 15) * 16 + aks) >> 2;
            const uint32_t* Asrc = half ? g_hh : g_aggh;
            const uint32_t* Bsrc = half ? Wo : Wr;
            na = arow ? __ldg((const uint2*)(Asrc + (size_t)gr * 128) + kc2)
                      : make_uint2(0u, 0u);
            nb0 = __ldg((const uint2*)(Bsrc + (size_t)am * 128) + kc2);
            nb1 = __ldg((const uint2*)(Bsrc + (size_t)(am + 128) * 128) + kc2);
        }
        __syncthreads();
        mma_slab(As, Bs, wm, wn, lane, c);
        ra = na; rb0 = nb0; rb1 = nb1;
    }

    float ps[8][2], pq[8][2];
#pragma unroll
    for (int nt = 0; nt < 8; nt++)
        ps[nt][0] = ps[nt][1] = pq[nt][0] = pq[nt][1] = 0.f;

#pragma unroll
    for (int mt = 0; mt < 2; mt++) {
        int row = bm + wm * 32 + mt * 16 + lq;
        bool v0 = row < N_NODES, v1 = (row + 8) < N_NODES;
#pragma unroll
        for (int nt = 0; nt < 8; nt++) {
            int col = wn * 64 + nt * 8 + lr * 2;
            float2 bb = __ldg((const float2*)(br + col));
            float o0 = c[mt][nt][0] + bb.x, o1 = c[mt][nt][1] + bb.y;
            float o2 = c[mt][nt][2] + bb.x, o3 = c[mt][nt][3] + bb.y;
            if (v0) {
                g_outh[(size_t)row * 128 + (col >> 1)] = pack_h2(o0, o1);
                ps[nt][0] += o0; pq[nt][0] += o0 * o0;
                ps[nt][1] += o1; pq[nt][1] += o1 * o1;
            }
            if (v1) {
                g_outh[(size_t)(row + 8) * 128 + (col >> 1)] = pack_h2(o2, o3);
                ps[nt][0] += o2; pq[nt][0] += o2 * o2;
                ps[nt][1] += o3; pq[nt][1] += o3 * o3;
            }
        }
    }
#pragma unroll
    for (int nt = 0; nt < 8; nt++)
#pragma unroll
        for (int u = 0; u < 2; u++) {
#pragma unroll
            for (int d = 4; d < 32; d <<= 1) {
                ps[nt][u] += __shfl_xor_sync(0xffffffffu, ps[nt][u], d);
                pq[nt][u] += __shfl_xor_sync(0xffffffffu, pq[nt][u], d);
            }
        }
    if (lq == 0) {
#pragma unroll
        for (int nt = 0; nt < 8; nt++) {
            int col = wn * 64 + nt * 8 + lr * 2;
            atomicAdd(&g_statsf[col], ps[nt][0]);
            atomicAdd(&g_statsf[col + 1], ps[nt][1]);
            atomicAdd(&g_statsf[HID + col], pq[nt][0]);
            atomicAdd(&g_statsf[HID + col + 1], pq[nt][1]);
        }
    }
}

// =================================================================
// fused edge MLP: z1 = relu(cat(hh[src],hh[dst])@W1^T+b1)  (smem)
//                 s  = relu(z1@W2^T+b2) . w3 ; out = sigmoid(s+b3)
// =================================================================
__global__ void __launch_bounds__(512, 1)
k_edge_fused(const int* __restrict__ ei, const float* __restrict__ b1,
             const float* __restrict__ b2, const float* __restrict__ W3,
             const float* __restrict__ b3, float* __restrict__ dout) {
    extern __shared__ uint32_t sm[];
    uint32_t* z1sm = sm;                 // 16 slabs x 1088
    uint32_t* bufs = sm + Z1U;           // 2 x STAGE
    __shared__ float sred[4][128];
    int tid = threadIdx.x;
    int bm = blockIdx.x * 128;
    int lane = tid & 31, lq = lane >> 2, lr = lane & 3;
    int wid = tid >> 5, wm = wid & 3, wn = wid >> 2;
    int am = tid >> 2, aks = (tid & 3) * 4;
    int k2 = aks >> 1;
    int e = bm + am;
    bool val = e < N_EDGES;
    int nsrc = val ? __ldg(ei + e) : 0;
    int ndst = val ? __ldg(ei + N_EDGES + e) : 0;
    float c[2][8][4] = {};

    // ---------------- stage 1: z1 = relu(cat @ W1^T + b1) ----------------
    uint2 ra, rb0, rb1;
    ra = val ? __ldg((const uint2*)(g_hh + (size_t)nsrc * 128) + k2 / 2)
             : make_uint2(0u, 0u);
    rb0 = __ldg((const uint2*)(g_W116 + (size_t)am * 256) + k2 / 2);
    rb1 = __ldg((const uint2*)(g_W116 + (size_t)(am + 128) * 256) + k2 / 2);

    for (int kt = 0; kt < 32; kt++) {
        int b = kt & 1;
        uint32_t* As = bufs + b * STAGE;
        uint32_t* Bs = As + ASLAB;
        store_slab(As, Bs, am, k2, ra, rb0, rb1);
        uint2 na = ra, nb0 = rb0, nb1 = rb1;
        if (kt < 31) {
            int kk = kt + 1;
            int half = kk >> 4;
            int node = half ? ndst : nsrc;
            int kc2a = ((kk & 15) * 16 + aks) >> 2;
            int kc2b = (kk * 16 + aks) >> 2;
            na = val ? __ldg((const uint2*)(g_hh + (size_t)node * 128) + kc2a)
                     : make_uint2(0u, 0u);
            nb0 = __ldg((const uint2*)(g_W116 + (size_t)am * 256) + kc2b);
            nb1 = __ldg((const uint2*)(g_W116 + (size_t)(am + 128) * 256) + kc2b);
        }
        __syncthreads();
        mma_slab(As, Bs, wm, wn, lane, c);
        ra = na; rb0 = nb0; rb1 = nb1;
    }

    // epilogue -> z1 tile in smem, stage-2 A layout: [col>>4][((col&15)>>1)*136 + row]
#pragma unroll
    for (int mt = 0; mt < 2; mt++) {
        int lrow = wm * 32 + mt * 16 + lq;
#pragma unroll
        for (int nt = 0; nt < 8; nt++) {
            int col = wn * 64 + nt * 8 + lr * 2;
            float2 bb = __ldg((const float2*)(b1 + col));
            uint32_t* dst = z1sm + (col >> 4) * ASLAB + ((col & 15) >> 1) * ASTR2;
            dst[lrow] = pack_h2(fmaxf(c[mt][nt][0] + bb.x, 0.f),
                                fmaxf(c[mt][nt][1] + bb.y, 0.f));
            dst[lrow + 8] = pack_h2(fmaxf(c[mt][nt][2] + bb.x, 0.f),
                                    fmaxf(c[mt][nt][3] + bb.y, 0.f));
        }
    }
    __syncthreads();   // z1 visible; buffers free for stage 2

    // ---------------- stage 2: z1 @ W2^T, dot w3, sigmoid ----------------
#pragma unroll
    for (int mt = 0; mt < 2; mt++)
#pragma unroll
        for (int nt = 0; nt < 8; nt++)
#pragma unroll
            for (int u = 0; u < 4; u++) c[mt][nt][u] = 0.f;

    rb0 = __ldg((const uint2*)(g_W216 + (size_t)am * 128) + k2 / 2);
    rb1 = __ldg((const uint2*)(g_W216 + (size_t)(am + 128) * 128) + k2 / 2);

    for (int kt = 0; kt < 16; kt++) {
        int b = kt & 1;
        uint32_t* Bs = bufs + b * STAGE + ASLAB;
        store_slab_b(Bs, am, k2, rb0, rb1);
        uint2 nb0 = rb0, nb1 = rb1;
        if (kt < 15) {
            int kc2 = ((kt + 1) * 16 + aks) >> 2;
            nb0 = __ldg((const uint2*)(g_W216 + (size_t)am * 128) + kc2);
            nb1 = __ldg((const uint2*)(g_W216 + (size_t)(am + 128) * 128) + kc2);
        }
        __syncthreads();
        mma_slab(z1sm + kt * ASLAB, Bs, wm, wn, lane, c);
        rb0 = nb0; rb1 = nb1;
        __syncthreads();   // mma done before next store to this buffer's pair
    }

#pragma unroll
    for (int mt = 0; mt < 2; mt++) {
        float p0 = 0.f, p1 = 0.f;
#pragma unroll
        for (int nt = 0; nt < 8; nt++) {
            int col = wn * 64 + nt * 8 + lr * 2;
            float2 bb = __ldg((const float2*)(b2 + col));
            float2 ww = __ldg((const float2*)(W3 + col));
            p0 = fmaf(fmaxf(c[mt][nt][0] + bb.x, 0.f), ww.x, p0);
            p0 = fmaf(fmaxf(c[mt][nt][1] + bb.y, 0.f), ww.y, p0);
            p1 = fmaf(fmaxf(c[mt][nt][2] + bb.x, 0.f), ww.x, p1);
            p1 = fmaf(fmaxf(c[mt][nt][3] + bb.y, 0.f), ww.y, p1);
        }
        p0 += __shfl_xor_sync(0xffffffffu, p0, 1);
        p0 += __shfl_xor_sync(0xffffffffu, p0, 2);
        p1 += __shfl_xor_sync(0xffffffffu, p1, 1);
        p1 += __shfl_xor_sync(0xffffffffu, p1, 2);
        if (lr == 0) {
            sred[wn][wm * 32 + mt * 16 + lq] = p0;
            sred[wn][wm * 32 + mt * 16 + lq + 8] = p1;
        }
    }
    __syncthreads();
    if (tid < 128) {
        int gr = bm + tid;
        if (gr < N_EDGES) {
            float s = sred[0][tid] + sred[1][tid] + sred[2][tid] + sred[3][tid] + __ldg(b3);
            dout[gr] = 1.f / (1.f + expf(-s));
        }
    }
}

// ---------------------------------------------------------------- launch
extern "C" void kernel_launch(void* const* d_in, const int* in_sizes, int n_in,
                              void* d_out, int out_size) {
    const float* x     = (const float*)d_in[0];
    const int*   ei    = (const int*)  d_in[1];
    const float* Win   = (const float*)d_in[2];
    const float* Wrel  = (const float*)d_in[3];
    const float* brel  = (const float*)d_in[4];
    const float* Wroot = (const float*)d_in[5];
    const float* gamma = (const float*)d_in[6];
    const float* beta  = (const float*)d_in[7];
    const float* W1    = (const float*)d_in[8];
    const float* b1    = (const float*)d_in[9];
    const float* W2    = (const float*)d_in[10];
    const float* b2    = (const float*)d_in[11];
    const float* W3    = (const float*)d_in[12];
    const float* b3    = (const float*)d_in[13];
    float* out = (float*)d_out;

    cudaFuncSetAttribute(k_gemm_node, cudaFuncAttributeMaxDynamicSharedMemorySize, SMEM_BYTES);
    cudaFuncSetAttribute(k_edge_fused, cudaFuncAttributeMaxDynamicSharedMemorySize, EDGE_SMEM);

    int ncvt = LAYERS * 256 * 128 + 256 * 256 + 256 * 128;
    k_cvt_weights<<<(ncvt + 255) / 256, 256>>>(Wrel, Wroot, W1, W2);
    k_input_fc<<<(N_NODES * 128 + 255) / 256, 256>>>(x, Win);
    k_csr_count<<<(N_EDGES + 255) / 256, 256>>>(ei);
    k_csr_scan<<<1, 1024>>>();
    k_csr_fill<<<(N_EDGES + 255) / 256, 256>>>(ei);

    int node_grid = (N_NODES + 127) / 128;     // 391
    int gather_grid = (N_NODES * 32 + 255) / 256;
    for (int l = 0; l < LAYERS; l++) {
        k_gather<<<gather_grid, 256>>>();
        k_gemm_node<<<node_grid, 512, SMEM_BYTES>>>(l, brel + (size_t)l * HID);
        k_bn_apply<<<(N_NODES * 128 + 255) / 256, 256>>>(
            gamma + (size_t)l * HID, beta + (size_t)l * HID);
    }

    int edge_grid = (N_EDGES + 127) / 128;     // 3907
    k_edge_fused<<<edge_grid, 512, EDGE_SMEM>>>(ei, b1, b2, W3, b3, out);
}

// round 9
// speedup vs baseline: 4.1210x; 1.0217x over previous
#include <cuda_runtime.h>
#include <cuda_fp16.h>
#include <cstdint>
#include <math.h>

#define N_NODES 50000
#define N_EDGES 500000
#define HID 256
#define LAYERS 15

// ---------------------------------------------------------------- scratch
__device__ float    g_h   [(size_t)N_NODES * HID];    // fp32 residual carry
__device__ uint32_t g_hh  [(size_t)N_NODES * 128];    // h as half2
__device__ uint32_t g_outh[(size_t)N_NODES * 128];    // pre-BN out as half2
__device__ float    g_statsf[LAYERS * 512];           // per-layer BN sum/sumsq
// fp16 weights
__device__ uint32_t g_Wrel16 [LAYERS * 256 * 128];
__device__ uint32_t g_Wroot16[LAYERS * 256 * 128];
__device__ uint32_t g_W116[256 * 256];
__device__ uint32_t g_W216[256 * 128];
// CSR
__device__ int g_deg[N_NODES];
__device__ int g_off[N_NODES + 1];
__device__ int g_pos[N_NODES];
__device__ int g_srcs[N_EDGES];

// ---------------------------------------------------------------- helpers
__device__ __forceinline__ uint32_t pack_h2(float x, float y) {
    __half2 h = __float22half2_rn(make_float2(x, y));
    return *(uint32_t*)&h;
}
__device__ __forceinline__ float2 unpack_h2(uint32_t u) {
    return __half22float2(*(__half2*)&u);
}
__device__ __forceinline__ void mma16(float* c, uint32_t a0, uint32_t a1,
                                      uint32_t a2, uint32_t a3,
                                      uint32_t b0, uint32_t b1) {
    asm volatile(
        "mma.sync.aligned.m16n8k16.row.col.f32.f16.f16.f32 "
        "{%0,%1,%2,%3}, {%4,%5,%6,%7}, {%8,%9}, {%0,%1,%2,%3};"
        : "+f"(c[0]), "+f"(c[1]), "+f"(c[2]), "+f"(c[3])
        : "r"(a0), "r"(a1), "r"(a2), "r"(a3), "r"(b0), "r"(b1));
}

// smem (half2 units):  A2[k2 8][row 128]  B2[k2 8][col 256], strides ≡ 8 mod 32
#define ASTR2 136
#define BSTR2 264
#define ASLAB (8 * ASTR2)              // 1088
#define BSLAB (8 * BSTR2)              // 2112
#define STAGE (ASLAB + BSLAB)          // 3200 uints (one 16-K slab A+B)
#define SCR_STR 132                    // gather scratch row stride (uint32)
#define NSMEM ((4 * STAGE + 128 * SCR_STR) * 4)   // 118784 B
#define Z1U (16 * ASLAB)               // 17408 uints
#define ESMEM ((Z1U + 4 * STAGE) * 4)  // 120832 B

__device__ __forceinline__ void store_slab(uint32_t* As, uint32_t* Bs, int am, int k2,
                                           uint2 ra, uint2 rb0, uint2 rb1) {
    As[(k2 + 0) * ASTR2 + am] = ra.x;
    As[(k2 + 1) * ASTR2 + am] = ra.y;
    Bs[(k2 + 0) * BSTR2 + am] = rb0.x;
    Bs[(k2 + 1) * BSTR2 + am] = rb0.y;
    Bs[(k2 + 0) * BSTR2 + am + 128] = rb1.x;
    Bs[(k2 + 1) * BSTR2 + am + 128] = rb1.y;
}
__device__ __forceinline__ void store_slab_b(uint32_t* Bs, int am, int k2,
                                             uint2 rb0, uint2 rb1) {
    Bs[(k2 + 0) * BSTR2 + am] = rb0.x;
    Bs[(k2 + 1) * BSTR2 + am] = rb0.y;
    Bs[(k2 + 0) * BSTR2 + am + 128] = rb1.x;
    Bs[(k2 + 1) * BSTR2 + am + 128] = rb1.y;
}

__device__ __forceinline__ void mma_slab(const uint32_t* As, const uint32_t* Bs,
                                         int wm, int wn, int lane,
                                         float c[2][8][4]) {
    int g = lane >> 2, t = lane & 3;
    uint32_t b0[8], b1[8];
#pragma unroll
    for (int nt = 0; nt < 8; nt++) {
        int C = wn * 64 + nt * 8 + g;
        b0[nt] = Bs[t * BSTR2 + C];
        b1[nt] = Bs[(t + 4) * BSTR2 + C];
    }
#pragma unroll
    for (int mt = 0; mt < 2; mt++) {
        int R = wm * 32 + mt * 16 + g;
        uint32_t a0 = As[t * ASTR2 + R];
        uint32_t a1 = As[t * ASTR2 + R + 8];
        uint32_t a2 = As[(t + 4) * ASTR2 + R];
        uint32_t a3 = As[(t + 4) * ASTR2 + R + 8];
#pragma unroll
        for (int nt = 0; nt < 8; nt++)
            mma16(c[mt][nt], a0, a1, a2, a3, b0[nt], b1[nt]);
    }
}

// ---------------------------------------------------------------- small kernels
__global__ void k_cvt_weights(const float* __restrict__ Wrel,
                              const float* __restrict__ Wroot,
                              const float* __restrict__ W1,
                              const float* __restrict__ W2) {
    const int NREL = LAYERS * 256 * 128;
    const int NW1 = 256 * 256;
    const int NW2 = 256 * 128;
    int i = blockIdx.x * blockDim.x + threadIdx.x;
    if (i < LAYERS * 512) g_statsf[i] = 0.f;
    if (i < NREL) {
        g_Wrel16[i] = pack_h2(Wrel[2 * i], Wrel[2 * i + 1]);
        g_Wroot16[i] = pack_h2(Wroot[2 * i], Wroot[2 * i + 1]);
    } else {
        int j = i - NREL;
        if (j < NW1) g_W116[j] = pack_h2(W1[2 * j], W1[2 * j + 1]);
        else if (j - NW1 < NW2) {
            int k = j - NW1;
            g_W216[k] = pack_h2(W2[2 * k], W2[2 * k + 1]);
        }
    }
}

__global__ void k_input_fc(const float* __restrict__ x, const float* __restrict__ Win) {
    int idx = blockIdx.x * blockDim.x + threadIdx.x;   // half2 units
    if (idx < N_NODES) g_deg[idx] = 0;
    if (idx >= N_NODES * 128) return;
    int node = idx >> 7, c0 = (idx & 127) * 2;
    float x0 = x[node * 2], x1 = x[node * 2 + 1];
    float h0 = x0 * Win[c0 * 2] + x1 * Win[c0 * 2 + 1];
    float h1 = x0 * Win[c0 * 2 + 2] + x1 * Win[c0 * 2 + 3];
    ((float2*)g_h)[idx] = make_float2(h0, h1);
    g_hh[idx] = pack_h2(h0, h1);
}

__global__ void k_csr_count(const int* __restrict__ ei) {
    int e = blockIdx.x * blockDim.x + threadIdx.x;
    if (e >= N_EDGES) return;
    atomicAdd(&g_deg[__ldg(ei + N_EDGES + e)], 1);
}

__global__ void k_csr_scan() {     // 1 block, 1024 threads
    __shared__ int wsum[32];
    __shared__ int s_carry;
    int tid = threadIdx.x, lane = tid & 31, wid = tid >> 5;
    if (tid == 0) s_carry = 0;
    __syncthreads();
    for (int base = 0; base < N_NODES; base += 1024) {
        int i = base + tid;
        int v = (i < N_NODES) ? g_deg[i] : 0;
        int x = v;
#pragma unroll
        for (int d = 1; d < 32; d <<= 1) {
            int y = __shfl_up_sync(0xffffffffu, x, d);
            if (lane >= d) x += y;
        }
        if (lane == 31) wsum[wid] = x;
        __syncthreads();
        if (wid == 0) {
            int w = wsum[lane];
#pragma unroll
            for (int d = 1; d < 32; d <<= 1) {
                int y = __shfl_up_sync(0xffffffffu, w, d);
                if (lane >= d) w += y;
            }
            wsum[lane] = w;
        }
        __syncthreads();
        int carry = s_carry;
        int incl = x + (wid > 0 ? wsum[wid - 1] : 0);
        if (i < N_NODES) {
            int excl = carry + incl - v;
            g_off[i] = excl;
            g_pos[i] = excl;
        }
        __syncthreads();
        if (tid == 0) s_carry = carry + wsum[31];
        __syncthreads();
    }
    if (threadIdx.x == 0) g_off[N_NODES] = s_carry;
}

__global__ void k_csr_fill(const int* __restrict__ ei) {
    int e = blockIdx.x * blockDim.x + threadIdx.x;
    if (e >= N_EDGES) return;
    int d = __ldg(ei + N_EDGES + e);
    int p = atomicAdd(&g_pos[d], 1);
    g_srcs[p] = __ldg(ei + e);
}

// ---- BN finalize + apply fused ----
__global__ void k_bn_apply(int layer, const float* __restrict__ gm,
                           const float* __restrict__ bt) {
    __shared__ float ssc[HID], ssh[HID];
    const float* stats = g_statsf + (size_t)layer * 512;
    int tid = threadIdx.x;
    if (tid < HID) {
        float mean = stats[tid] * (1.f / N_NODES);
        float var  = stats[HID + tid] * (1.f / N_NODES) - mean * mean;
        float rstd = rsqrtf(var + 1e-5f);
        float sc = rstd * __ldg(gm + tid);
        ssc[tid] = sc;
        ssh[tid] = __ldg(bt + tid) - mean * sc;
    }
    __syncthreads();
    int idx = blockIdx.x * blockDim.x + tid;
    if (idx >= N_NODES * 128) return;
    int c0 = (idx & 127) * 2;
    float2 o = unpack_h2(g_outh[idx]);
    float2 hv = ((float2*)g_h)[idx];
    hv.x += fmaxf(fmaf(o.x, ssc[c0], ssh[c0]), 0.f);
    hv.y += fmaxf(fmaf(o.y, ssc[c0 + 1], ssh[c0 + 1]), 0.f);
    ((float2*)g_h)[idx] = hv;
    g_hh[idx] = pack_h2(hv.x, hv.y);
}

// =================================================================
// node layer: phase 0 gathers agg for this block's rows into smem,
// then BK=32 double-buffered fp16 GEMM, fused BN stats epilogue.
// =================================================================
__global__ void __launch_bounds__(512, 1)
k_gemm_node(int layer, const float* __restrict__ br) {
    extern __shared__ uint32_t sm[];
    uint32_t* bufs = sm;                  // 4 * STAGE
    uint32_t* scr  = sm + 4 * STAGE;      // 128 * SCR_STR (agg rows, half2)
    int tid = threadIdx.x;
    int bm = blockIdx.x * 128;
    int lane = tid & 31, lq = lane >> 2, lr = lane & 3;
    int wid = tid >> 5, wm = wid & 3, wn = wid >> 2;
    int am = tid >> 2, aks = (tid & 3) * 4;
    int k2 = aks >> 1;
    int gr = bm + am;
    bool arow = gr < N_NODES;
    const uint32_t* Wr = g_Wrel16 + (size_t)layer * 256 * 128;
    const uint32_t* Wo = g_Wroot16 + (size_t)layer * 256 * 128;
    float* stats = g_statsf + (size_t)layer * 512;

    // ---- phase 0: gather (warp per node, 8 nodes per warp) ----
    {
        const uint4* hp = (const uint4*)g_hh;
        for (int i = 0; i < 8; i++) {
            int row = wid * 8 + i;
            int node = bm + row;
            float acc[8] = {};
            if (node < N_NODES) {
                int beg = g_off[node], end = g_off[node + 1];
                int t = beg;
                for (; t + 1 < end; t += 2) {
                    int s0 = __ldg(&g_srcs[t]);
                    int s1 = __ldg(&g_srcs[t + 1]);
                    uint4 v0 = __ldg(hp + (size_t)s0 * 32 + lane);
                    uint4 v1 = __ldg(hp + (size_t)s1 * 32 + lane);
                    float2 f;
                    f = unpack_h2(v0.x); acc[0] += f.x; acc[1] += f.y;
                    f = unpack_h2(v0.y); acc[2] += f.x; acc[3] += f.y;
                    f = unpack_h2(v0.z); acc[4] += f.x; acc[5] += f.y;
                    f = unpack_h2(v0.w); acc[6] += f.x; acc[7] += f.y;
                    f = unpack_h2(v1.x); acc[0] += f.x; acc[1] += f.y;
                    f = unpack_h2(v1.y); acc[2] += f.x; acc[3] += f.y;
                    f = unpack_h2(v1.z); acc[4] += f.x; acc[5] += f.y;
                    f = unpack_h2(v1.w); acc[6] += f.x; acc[7] += f.y;
                }
                if (t < end) {
                    int s0 = __ldg(&g_srcs[t]);
                    uint4 v0 = __ldg(hp + (size_t)s0 * 32 + lane);
                    float2 f;
                    f = unpack_h2(v0.x); acc[0] += f.x; acc[1] += f.y;
                    f = unpack_h2(v0.y); acc[2] += f.x; acc[3] += f.y;
                    f = unpack_h2(v0.z); acc[4] += f.x; acc[5] += f.y;
                    f = unpack_h2(v0.w); acc[6] += f.x; acc[7] += f.y;
                }
            }
            uint4 o;
            o.x = pack_h2(acc[0], acc[1]);
            o.y = pack_h2(acc[2], acc[3]);
            o.z = pack_h2(acc[4], acc[5]);
            o.w = pack_h2(acc[6], acc[7]);
            *(uint4*)(scr + row * SCR_STR + lane * 4) = o;
        }
    }
    __syncthreads();

    // ---- mainloop: 16 stages x 32 K ----
    float c[2][8][4] = {};
    uint2 ra[2], rb0[2], rb1[2];
#pragma unroll
    for (int j = 0; j < 2; j++) {
        int hoff = j * 16 + aks;
        int kc2 = hoff >> 2;
        ra[j] = *(const uint2*)(scr + am * SCR_STR + (hoff >> 1));
        rb0[j] = __ldg((const uint2*)(Wr + (size_t)am * 128) + kc2);
        rb1[j] = __ldg((const uint2*)(Wr + (size_t)(am + 128) * 128) + kc2);
    }
    for (int st = 0; st < 16; st++) {
        int b = st & 1;
        uint32_t* s0 = bufs + b * 2 * STAGE;
        uint32_t* s1 = s0 + STAGE;
        store_slab(s0, s0 + ASLAB, am, k2, ra[0], rb0[0], rb1[0]);
        store_slab(s1, s1 + ASLAB, am, k2, ra[1], rb0[1], rb1[1]);
        uint2 na[2] = {ra[0], ra[1]}, nb0[2] = {rb0[0], rb0[1]}, nb1[2] = {rb1[0], rb1[1]};
        if (st < 15) {
#pragma unroll
            for (int j = 0; j < 2; j++) {
                int kk = 2 * st + 2 + j;
                int half = kk >> 4;
                int hoff = (kk & 15) * 16 + aks;
                int kc2 = hoff >> 2;
                if (half == 0) {
                    na[j] = *(const uint2*)(scr + am * SCR_STR + (hoff >> 1));
                    nb0[j] = __ldg((const uint2*)(Wr + (size_t)am * 128) + kc2);
                    nb1[j] = __ldg((const uint2*)(Wr + (size_t)(am + 128) * 128) + kc2);
                } else {
                    na[j] = arow ? __ldg((const uint2*)(g_hh + (size_t)gr * 128) + kc2)
                                 : make_uint2(0u, 0u);
                    nb0[j] = __ldg((const uint2*)(Wo + (size_t)am * 128) + kc2);
                    nb1[j] = __ldg((const uint2*)(Wo + (size_t)(am + 128) * 128) + kc2);
                }
            }
        }
        __syncthreads();
        mma_slab(s0, s0 + ASLAB, wm, wn, lane, c);
        mma_slab(s1, s1 + ASLAB, wm, wn, lane, c);
        ra[0] = na[0]; ra[1] = na[1];
        rb0[0] = nb0[0]; rb0[1] = nb0[1];
        rb1[0] = nb1[0]; rb1[1] = nb1[1];
    }

    // ---- epilogue: +br, store g_outh, accumulate BN stats ----
    float ps[8][2], pq[8][2];
#pragma unroll
    for (int nt = 0; nt < 8; nt++)
        ps[nt][0] = ps[nt][1] = pq[nt][0] = pq[nt][1] = 0.f;

#pragma unroll
    for (int mt = 0; mt < 2; mt++) {
        int row = bm + wm * 32 + mt * 16 + lq;
        bool v0 = row < N_NODES, v1 = (row + 8) < N_NODES;
#pragma unroll
        for (int nt = 0; nt < 8; nt++) {
            int col = wn * 64 + nt * 8 + lr * 2;
            float2 bb = __ldg((const float2*)(br + col));
            float o0 = c[mt][nt][0] + bb.x, o1 = c[mt][nt][1] + bb.y;
            float o2 = c[mt][nt][2] + bb.x, o3 = c[mt][nt][3] + bb.y;
            if (v0) {
                g_outh[(size_t)row * 128 + (col >> 1)] = pack_h2(o0, o1);
                ps[nt][0] += o0; pq[nt][0] += o0 * o0;
                ps[nt][1] += o1; pq[nt][1] += o1 * o1;
            }
            if (v1) {
                g_outh[(size_t)(row + 8) * 128 + (col >> 1)] = pack_h2(o2, o3);
                ps[nt][0] += o2; pq[nt][0] += o2 * o2;
                ps[nt][1] += o3; pq[nt][1] += o3 * o3;
            }
        }
    }
#pragma unroll
    for (int nt = 0; nt < 8; nt++)
#pragma unroll
        for (int u = 0; u < 2; u++) {
#pragma unroll
            for (int d = 4; d < 32; d <<= 1) {
                ps[nt][u] += __shfl_xor_sync(0xffffffffu, ps[nt][u], d);
                pq[nt][u] += __shfl_xor_sync(0xffffffffu, pq[nt][u], d);
            }
        }
    if (lq == 0) {
#pragma unroll
        for (int nt = 0; nt < 8; nt++) {
            int col = wn * 64 + nt * 8 + lr * 2;
            atomicAdd(&stats[col], ps[nt][0]);
            atomicAdd(&stats[col + 1], ps[nt][1]);
            atomicAdd(&stats[HID + col], pq[nt][0]);
            atomicAdd(&stats[HID + col + 1], pq[nt][1]);
        }
    }
}

// =================================================================
// fused edge MLP (BK=32 stages):
//   z1 = relu(cat(hh[src],hh[dst])@W1^T+b1)  (kept in smem)
//   s  = relu(z1@W2^T+b2) . w3 ; out = sigmoid(s+b3)
// =================================================================
__global__ void __launch_bounds__(512, 1)
k_edge_fused(const int* __restrict__ ei, const float* __restrict__ b1,
             const float* __restrict__ b2, const float* __restrict__ W3,
             const float* __restrict__ b3, float* __restrict__ dout) {
    extern __shared__ uint32_t sm[];
    uint32_t* z1sm = sm;                 // 16 slabs x ASLAB
    uint32_t* bufs = sm + Z1U;           // 4 * STAGE
    __shared__ float sred[4][128];
    int tid = threadIdx.x;
    int bm = blockIdx.x * 128;
    int lane = tid & 31, lq = lane >> 2, lr = lane & 3;
    int wid = tid >> 5, wm = wid & 3, wn = wid >> 2;
    int am = tid >> 2, aks = (tid & 3) * 4;
    int k2 = aks >> 1;
    int e = bm + am;
    bool val = e < N_EDGES;
    int nsrc = val ? __ldg(ei + e) : 0;
    int ndst = val ? __ldg(ei + N_EDGES + e) : 0;
    float c[2][8][4] = {};

    // ---------------- stage 1: z1 = relu(cat @ W1^T + b1) ----------------
    uint2 ra[2], rb0[2], rb1[2];
#pragma unroll
    for (int j = 0; j < 2; j++) {
        int kc2 = (j * 16 + aks) >> 2;
        ra[j] = val ? __ldg((const uint2*)(g_hh + (size_t)nsrc * 128) + kc2)
                    : make_uint2(0u, 0u);
        rb0[j] = __ldg((const uint2*)(g_W116 + (size_t)am * 256) + kc2);
        rb1[j] = __ldg((const uint2*)(g_W116 + (size_t)(am + 128) * 256) + kc2);
    }
    for (int st = 0; st < 16; st++) {
        int b = st & 1;
        uint32_t* s0 = bufs + b * 2 * STAGE;
        uint32_t* s1 = s0 + STAGE;
        store_slab(s0, s0 + ASLAB, am, k2, ra[0], rb0[0], rb1[0]);
        store_slab(s1, s1 + ASLAB, am, k2, ra[1], rb0[1], rb1[1]);
        uint2 na[2] = {ra[0], ra[1]}, nb0[2] = {rb0[0], rb0[1]}, nb1[2] = {rb1[0], rb1[1]};
        if (st < 15) {
#pragma unroll
            for (int j = 0; j < 2; j++) {
                int kk = 2 * st + 2 + j;
                int half = kk >> 4;
                int node = half ? ndst : nsrc;
                int kc2a = ((kk & 15) * 16 + aks) >> 2;
                int kc2b = (kk * 16 + aks) >> 2;
                na[j] = val ? __ldg((const uint2*)(g_hh + (size_t)node * 128) + kc2a)
                            : make_uint2(0u, 0u);
                nb0[j] = __ldg((const uint2*)(g_W116 + (size_t)am * 256) + kc2b);
                nb1[j] = __ldg((const uint2*)(g_W116 + (size_t)(am + 128) * 256) + kc2b);
            }
        }
        __syncthreads();
        mma_slab(s0, s0 + ASLAB, wm, wn, lane, c);
        mma_slab(s1, s1 + ASLAB, wm, wn, lane, c);
        ra[0] = na[0]; ra[1] = na[1];
        rb0[0] = nb0[0]; rb0[1] = nb0[1];
        rb1[0] = nb1[0]; rb1[1] = nb1[1];
    }

    // epilogue -> z1 tile in smem (stage-2 A fragment layout)
#pragma unroll
    for (int mt = 0; mt < 2; mt++) {
        int lrow = wm * 32 + mt * 16 + lq;
#pragma unroll
        for (int nt = 0; nt < 8; nt++) {
            int col = wn * 64 + nt * 8 + lr * 2;
            float2 bb = __ldg((const float2*)(b1 + col));
            uint32_t* dst = z1sm + (col >> 4) * ASLAB + ((col & 15) >> 1) * ASTR2;
            dst[lrow] = pack_h2(fmaxf(c[mt][nt][0] + bb.x, 0.f),
                                fmaxf(c[mt][nt][1] + bb.y, 0.f));
            dst[lrow + 8] = pack_h2(fmaxf(c[mt][nt][2] + bb.x, 0.f),
                                    fmaxf(c[mt][nt][3] + bb.y, 0.f));
        }
    }
    __syncthreads();   // z1 visible; buffers free

    // ---------------- stage 2: z1 @ W2^T, dot w3, sigmoid ----------------
#pragma unroll
    for (int mt = 0; mt < 2; mt++)
#pragma unroll
        for (int nt = 0; nt < 8; nt++)
#pragma unroll
            for (int u = 0; u < 4; u++) c[mt][nt][u] = 0.f;

    uint2 qb0[2], qb1[2];
#pragma unroll
    for (int j = 0; j < 2; j++) {
        int kc2 = (j * 16 + aks) >> 2;
        qb0[j] = __ldg((const uint2*)(g_W216 + (size_t)am * 128) + kc2);
        qb1[j] = __ldg((const uint2*)(g_W216 + (size_t)(am + 128) * 128) + kc2);
    }
    for (int st = 0; st < 8; st++) {
        int b = st & 1;
        uint32_t* B0 = bufs + b * 2 * BSLAB;
        uint32_t* B1 = B0 + BSLAB;
        store_slab_b(B0, am, k2, qb0[0], qb1[0]);
        store_slab_b(B1, am, k2, qb0[1], qb1[1]);
        uint2 n0[2] = {qb0[0], qb0[1]}, n1[2] = {qb1[0], qb1[1]};
        if (st < 7) {
#pragma unroll
            for (int j = 0; j < 2; j++) {
                int kc2 = ((2 * st + 2 + j) * 16 + aks) >> 2;
                n0[j] = __ldg((const uint2*)(g_W216 + (size_t)am * 128) + kc2);
                n1[j] = __ldg((const uint2*)(g_W216 + (size_t)(am + 128) * 128) + kc2);
            }
        }
        __syncthreads();
        mma_slab(z1sm + (2 * st) * ASLAB, B0, wm, wn, lane, c);
        mma_slab(z1sm + (2 * st + 1) * ASLAB, B1, wm, wn, lane, c);
        qb0[0] = n0[0]; qb0[1] = n0[1];
        qb1[0] = n1[0]; qb1[1] = n1[1];
    }

#pragma unroll
    for (int mt = 0; mt < 2; mt++) {
        float p0 = 0.f, p1 = 0.f;
#pragma unroll
        for (int nt = 0; nt < 8; nt++) {
            int col = wn * 64 + nt * 8 + lr * 2;
            float2 bb = __ldg((const float2*)(b2 + col));
            float2 ww = __ldg((const float2*)(W3 + col));
            p0 = fmaf(fmaxf(c[mt][nt][0] + bb.x, 0.f), ww.x, p0);
            p0 = fmaf(fmaxf(c[mt][nt][1] + bb.y, 0.f), ww.y, p0);
            p1 = fmaf(fmaxf(c[mt][nt][2] + bb.x, 0.f), ww.x, p1);
            p1 = fmaf(fmaxf(c[mt][nt][3] + bb.y, 0.f), ww.y, p1);
        }
        p0 += __shfl_xor_sync(0xffffffffu, p0, 1);
        p0 += __shfl_xor_sync(0xffffffffu, p0, 2);
        p1 += __shfl_xor_sync(0xffffffffu, p1, 1);
        p1 += __shfl_xor_sync(0xffffffffu, p1, 2);
        if (lr == 0) {
            sred[wn][wm * 32 + mt * 16 + lq] = p0;
            sred[wn][wm * 32 + mt * 16 + lq + 8] = p1;
        }
    }
    __syncthreads();
    if (tid < 128) {
        int gr = bm + tid;
        if (gr < N_EDGES) {
            float s = sred[0][tid] + sred[1][tid] + sred[2][tid] + sred[3][tid] + __ldg(b3);
            dout[gr] = 1.f / (1.f + expf(-s));
        }
    }
}

// ---------------------------------------------------------------- launch
extern "C" void kernel_launch(void* const* d_in, const int* in_sizes, int n_in,
                              void* d_out, int out_size) {
    const float* x     = (const float*)d_in[0];
    const int*   ei    = (const int*)  d_in[1];
    const float* Win   = (const float*)d_in[2];
    const float* Wrel  = (const float*)d_in[3];
    const float* brel  = (const float*)d_in[4];
    const float* Wroot = (const float*)d_in[5];
    const float* gamma = (const float*)d_in[6];
    const float* beta  = (const float*)d_in[7];
    const float* W1    = (const float*)d_in[8];
    const float* b1    = (const float*)d_in[9];
    const float* W2    = (const float*)d_in[10];
    const float* b2    = (const float*)d_in[11];
    const float* W3    = (const float*)d_in[12];
    const float* b3    = (const float*)d_in[13];
    float* out = (float*)d_out;

    cudaFuncSetAttribute(k_gemm_node, cudaFuncAttributeMaxDynamicSharedMemorySize, NSMEM);
    cudaFuncSetAttribute(k_edge_fused, cudaFuncAttributeMaxDynamicSharedMemorySize, ESMEM);

    int ncvt = LAYERS * 256 * 128 + 256 * 256 + 256 * 128;
    k_cvt_weights<<<(ncvt + 255) / 256, 256>>>(Wrel, Wroot, W1, W2);
    k_input_fc<<<(N_NODES * 128 + 255) / 256, 256>>>(x, Win);
    k_csr_count<<<(N_EDGES + 255) / 256, 256>>>(ei);
    k_csr_scan<<<1, 1024>>>();
    k_csr_fill<<<(N_EDGES + 255) / 256, 256>>>(ei);

    int node_grid = (N_NODES + 127) / 128;     // 391
    for (int l = 0; l < LAYERS; l++) {
        k_gemm_node<<<node_grid, 512, NSMEM>>>(l, brel + (size_t)l * HID);
        k_bn_apply<<<(N_NODES * 128 + 255) / 256, 256>>>(
            l, gamma + (size_t)l * HID, beta + (size_t)l * HID);
    }

    int edge_grid = (N_EDGES + 127) / 128;     // 3907
    k_edge_fused<<<edge_grid, 512, ESMEM>>>(ei, b1, b2, W3, b3, out);
}

// round 10
// speedup vs baseline: 4.6481x; 1.1279x over previous
#include <cuda_runtime.h>
#include <cuda_fp16.h>
#include <cstdint>
#include <math.h>

#define N_NODES 50000
#define N_EDGES 500000
#define HID 256
#define LAYERS 15

// ---------------------------------------------------------------- scratch
__device__ float    g_h   [(size_t)N_NODES * HID];    // fp32 residual carry
__device__ uint32_t g_hh  [(size_t)N_NODES * 128];    // h as half2
__device__ uint32_t g_outh[(size_t)N_NODES * 128];    // pre-BN out as half2
__device__ uint32_t g_uv  [(size_t)N_NODES * 256];    // U|V per node (half2)
__device__ float    g_statsf[LAYERS * 512];           // per-layer BN sum/sumsq
// fp16 weights
__device__ uint32_t g_Wrel16 [LAYERS * 256 * 128];
__device__ uint32_t g_Wroot16[LAYERS * 256 * 128];
__device__ uint32_t g_W116[256 * 256];
__device__ uint32_t g_W216[256 * 128];
// CSR
__device__ int g_deg[N_NODES];
__device__ int g_off[N_NODES + 1];
__device__ int g_pos[N_NODES];
__device__ int g_srcs[N_EDGES];

// ---------------------------------------------------------------- helpers
__device__ __forceinline__ uint32_t pack_h2(float x, float y) {
    __half2 h = __float22half2_rn(make_float2(x, y));
    return *(uint32_t*)&h;
}
__device__ __forceinline__ float2 unpack_h2(uint32_t u) {
    return __half22float2(*(__half2*)&u);
}
__device__ __forceinline__ void mma16(float* c, uint32_t a0, uint32_t a1,
                                      uint32_t a2, uint32_t a3,
                                      uint32_t b0, uint32_t b1) {
    asm volatile(
        "mma.sync.aligned.m16n8k16.row.col.f32.f16.f16.f32 "
        "{%0,%1,%2,%3}, {%4,%5,%6,%7}, {%8,%9}, {%0,%1,%2,%3};"
        : "+f"(c[0]), "+f"(c[1]), "+f"(c[2]), "+f"(c[3])
        : "r"(a0), "r"(a1), "r"(a2), "r"(a3), "r"(b0), "r"(b1));
}

// smem (half2 units):  A2[k2 8][row 128]  B2[k2 8][col 256], strides ≡ 8 mod 32
#define ASTR2 136
#define BSTR2 264
#define ASLAB (8 * ASTR2)              // 1088
#define BSLAB (8 * BSTR2)              // 2112
#define STAGE (ASLAB + BSLAB)          // 3200 uints (one 16-K slab A+B)
#define SCR_STR 132                    // gather scratch row stride (uint32)
#define NSMEM ((4 * STAGE + 128 * SCR_STR) * 4)   // 118784 B
#define UVSMEM (4 * STAGE * 4)         // 51200 B
#define SL 1096                        // z1 slab stride (padded: conflict-free fill)
#define Z1U2 (16 * SL)                 // 17536
#define ESMEM ((Z1U2 + 4 * BSLAB) * 4) // 103936 B

__device__ __forceinline__ void store_slab(uint32_t* As, uint32_t* Bs, int am, int k2,
                                           uint2 ra, uint2 rb0, uint2 rb1) {
    As[(k2 + 0) * ASTR2 + am] = ra.x;
    As[(k2 + 1) * ASTR2 + am] = ra.y;
    Bs[(k2 + 0) * BSTR2 + am] = rb0.x;
    Bs[(k2 + 1) * BSTR2 + am] = rb0.y;
    Bs[(k2 + 0) * BSTR2 + am + 128] = rb1.x;
    Bs[(k2 + 1) * BSTR2 + am + 128] = rb1.y;
}
__device__ __forceinline__ void store_slab_b(uint32_t* Bs, int am, int k2,
                                             uint2 rb0, uint2 rb1) {
    Bs[(k2 + 0) * BSTR2 + am] = rb0.x;
    Bs[(k2 + 1) * BSTR2 + am] = rb0.y;
    Bs[(k2 + 0) * BSTR2 + am + 128] = rb1.x;
    Bs[(k2 + 1) * BSTR2 + am + 128] = rb1.y;
}

__device__ __forceinline__ void mma_slab(const uint32_t* As, const uint32_t* Bs,
                                         int wm, int wn, int lane,
                                         float c[2][8][4]) {
    int g = lane >> 2, t = lane & 3;
    uint32_t b0[8], b1[8];
#pragma unroll
    for (int nt = 0; nt < 8; nt++) {
        int C = wn * 64 + nt * 8 + g;
        b0[nt] = Bs[t * BSTR2 + C];
        b1[nt] = Bs[(t + 4) * BSTR2 + C];
    }
#pragma unroll
    for (int mt = 0; mt < 2; mt++) {
        int R = wm * 32 + mt * 16 + g;
        uint32_t a0 = As[t * ASTR2 + R];
        uint32_t a1 = As[t * ASTR2 + R + 8];
        uint32_t a2 = As[(t + 4) * ASTR2 + R];
        uint32_t a3 = As[(t + 4) * ASTR2 + R + 8];
#pragma unroll
        for (int nt = 0; nt < 8; nt++)
            mma16(c[mt][nt], a0, a1, a2, a3, b0[nt], b1[nt]);
    }
}

// ---------------------------------------------------------------- small kernels
__global__ void k_cvt_weights(const float* __restrict__ Wrel,
                              const float* __restrict__ Wroot,
                              const float* __restrict__ W1,
                              const float* __restrict__ W2) {
    const int NREL = LAYERS * 256 * 128;
    const int NW1 = 256 * 256;
    const int NW2 = 256 * 128;
    int i = blockIdx.x * blockDim.x + threadIdx.x;
    if (i < LAYERS * 512) g_statsf[i] = 0.f;
    if (i < NREL) {
        g_Wrel16[i] = pack_h2(Wrel[2 * i], Wrel[2 * i + 1]);
        g_Wroot16[i] = pack_h2(Wroot[2 * i], Wroot[2 * i + 1]);
    } else {
        int j = i - NREL;
        if (j < NW1) g_W116[j] = pack_h2(W1[2 * j], W1[2 * j + 1]);
        else if (j - NW1 < NW2) {
            int k = j - NW1;
            g_W216[k] = pack_h2(W2[2 * k], W2[2 * k + 1]);
        }
    }
}

__global__ void k_input_fc(const float* __restrict__ x, const float* __restrict__ Win) {
    int idx = blockIdx.x * blockDim.x + threadIdx.x;   // half2 units
    if (idx < N_NODES) g_deg[idx] = 0;
    if (idx >= N_NODES * 128) return;
    int node = idx >> 7, c0 = (idx & 127) * 2;
    float x0 = x[node * 2], x1 = x[node * 2 + 1];
    float h0 = x0 * Win[c0 * 2] + x1 * Win[c0 * 2 + 1];
    float h1 = x0 * Win[c0 * 2 + 2] + x1 * Win[c0 * 2 + 3];
    ((float2*)g_h)[idx] = make_float2(h0, h1);
    g_hh[idx] = pack_h2(h0, h1);
}

__global__ void k_csr_count(const int* __restrict__ ei) {
    int e = blockIdx.x * blockDim.x + threadIdx.x;
    if (e >= N_EDGES) return;
    atomicAdd(&g_deg[__ldg(ei + N_EDGES + e)], 1);
}

__global__ void k_csr_scan() {     // 1 block, 1024 threads
    __shared__ int wsum[32];
    __shared__ int s_carry;
    int tid = threadIdx.x, lane = tid & 31, wid = tid >> 5;
    if (tid == 0) s_carry = 0;
    __syncthreads();
    for (int base = 0; base < N_NODES; base += 1024) {
        int i = base + tid;
        int v = (i < N_NODES) ? g_deg[i] : 0;
        int x = v;
#pragma unroll
        for (int d = 1; d < 32; d <<= 1) {
            int y = __shfl_up_sync(0xffffffffu, x, d);
            if (lane >= d) x += y;
        }
        if (lane == 31) wsum[wid] = x;
        __syncthreads();
        if (wid == 0) {
            int w = wsum[lane];
#pragma unroll
            for (int d = 1; d < 32; d <<= 1) {
                int y = __shfl_up_sync(0xffffffffu, w, d);
                if (lane >= d) w += y;
            }
            wsum[lane] = w;
        }
        __syncthreads();
        int carry = s_carry;
        int incl = x + (wid > 0 ? wsum[wid - 1] : 0);
        if (i < N_NODES) {
            int excl = carry + incl - v;
            g_off[i] = excl;
            g_pos[i] = excl;
        }
        __syncthreads();
        if (tid == 0) s_carry = carry + wsum[31];
        __syncthreads();
    }
    if (threadIdx.x == 0) g_off[N_NODES] = s_carry;
}

__global__ void k_csr_fill(const int* __restrict__ ei) {
    int e = blockIdx.x * blockDim.x + threadIdx.x;
    if (e >= N_EDGES) return;
    int d = __ldg(ei + N_EDGES + e);
    int p = atomicAdd(&g_pos[d], 1);
    g_srcs[p] = __ldg(ei + e);
}

// ---- BN finalize + apply fused ----
__global__ void k_bn_apply(int layer, const float* __restrict__ gm,
                           const float* __restrict__ bt) {
    __shared__ float ssc[HID], ssh[HID];
    const float* stats = g_statsf + (size_t)layer * 512;
    int tid = threadIdx.x;
    if (tid < HID) {
        float mean = stats[tid] * (1.f / N_NODES);
        float var  = stats[HID + tid] * (1.f / N_NODES) - mean * mean;
        float rstd = rsqrtf(var + 1e-5f);
        float sc = rstd * __ldg(gm + tid);
        ssc[tid] = sc;
        ssh[tid] = __ldg(bt + tid) - mean * sc;
    }
    __syncthreads();
    int idx = blockIdx.x * blockDim.x + tid;
    if (idx >= N_NODES * 128) return;
    int c0 = (idx & 127) * 2;
    float2 o = unpack_h2(g_outh[idx]);
    float2 hv = ((float2*)g_h)[idx];
    hv.x += fmaxf(fmaf(o.x, ssc[c0], ssh[c0]), 0.f);
    hv.y += fmaxf(fmaf(o.y, ssc[c0 + 1], ssh[c0 + 1]), 0.f);
    ((float2*)g_h)[idx] = hv;
    g_hh[idx] = pack_h2(hv.x, hv.y);
}

// =================================================================
// node layer: phase 0 gathers agg into smem, BK=32 fp16 GEMM,
// fused BN stats epilogue. (unchanged from R9)
// =================================================================
__global__ void __launch_bounds__(512, 1)
k_gemm_node(int layer, const float* __restrict__ br) {
    extern __shared__ uint32_t sm[];
    uint32_t* bufs = sm;
    uint32_t* scr  = sm + 4 * STAGE;
    int tid = threadIdx.x;
    int bm = blockIdx.x * 128;
    int lane = tid & 31, lq = lane >> 2, lr = lane & 3;
    int wid = tid >> 5, wm = wid & 3, wn = wid >> 2;
    int am = tid >> 2, aks = (tid & 3) * 4;
    int k2 = aks >> 1;
    int gr = bm + am;
    bool arow = gr < N_NODES;
    const uint32_t* Wr = g_Wrel16 + (size_t)layer * 256 * 128;
    const uint32_t* Wo = g_Wroot16 + (size_t)layer * 256 * 128;
    float* stats = g_statsf + (size_t)layer * 512;

    // ---- phase 0: gather ----
    {
        const uint4* hp = (const uint4*)g_hh;
        for (int i = 0; i < 8; i++) {
            int row = wid * 8 + i;
            int node = bm + row;
            float acc[8] = {};
            if (node < N_NODES) {
                int beg = g_off[node], end = g_off[node + 1];
                int t = beg;
                for (; t + 1 < end; t += 2) {
                    int s0 = __ldg(&g_srcs[t]);
                    int s1 = __ldg(&g_srcs[t + 1]);
                    uint4 v0 = __ldg(hp + (size_t)s0 * 32 + lane);
                    uint4 v1 = __ldg(hp + (size_t)s1 * 32 + lane);
                    float2 f;
                    f = unpack_h2(v0.x); acc[0] += f.x; acc[1] += f.y;
                    f = unpack_h2(v0.y); acc[2] += f.x; acc[3] += f.y;
                    f = unpack_h2(v0.z); acc[4] += f.x; acc[5] += f.y;
                    f = unpack_h2(v0.w); acc[6] += f.x; acc[7] += f.y;
                    f = unpack_h2(v1.x); acc[0] += f.x; acc[1] += f.y;
                    f = unpack_h2(v1.y); acc[2] += f.x; acc[3] += f.y;
                    f = unpack_h2(v1.z); acc[4] += f.x; acc[5] += f.y;
                    f = unpack_h2(v1.w); acc[6] += f.x; acc[7] += f.y;
                }
                if (t < end) {
                    int s0 = __ldg(&g_srcs[t]);
                    uint4 v0 = __ldg(hp + (size_t)s0 * 32 + lane);
                    float2 f;
                    f = unpack_h2(v0.x); acc[0] += f.x; acc[1] += f.y;
                    f = unpack_h2(v0.y); acc[2] += f.x; acc[3] += f.y;
                    f = unpack_h2(v0.z); acc[4] += f.x; acc[5] += f.y;
                    f = unpack_h2(v0.w); acc[6] += f.x; acc[7] += f.y;
                }
            }
            uint4 o;
            o.x = pack_h2(acc[0], acc[1]);
            o.y = pack_h2(acc[2], acc[3]);
            o.z = pack_h2(acc[4], acc[5]);
            o.w = pack_h2(acc[6], acc[7]);
            *(uint4*)(scr + row * SCR_STR + lane * 4) = o;
        }
    }
    __syncthreads();

    // ---- mainloop: 16 stages x 32 K ----
    float c[2][8][4] = {};
    uint2 ra[2], rb0[2], rb1[2];
#pragma unroll
    for (int j = 0; j < 2; j++) {
        int hoff = j * 16 + aks;
        int kc2 = hoff >> 2;
        ra[j] = *(const uint2*)(scr + am * SCR_STR + (hoff >> 1));
        rb0[j] = __ldg((const uint2*)(Wr + (size_t)am * 128) + kc2);
        rb1[j] = __ldg((const uint2*)(Wr + (size_t)(am + 128) * 128) + kc2);
    }
    for (int st = 0; st < 16; st++) {
        int b = st & 1;
        uint32_t* s0 = bufs + b * 2 * STAGE;
        uint32_t* s1 = s0 + STAGE;
        store_slab(s0, s0 + ASLAB, am, k2, ra[0], rb0[0], rb1[0]);
        store_slab(s1, s1 + ASLAB, am, k2, ra[1], rb0[1], rb1[1]);
        uint2 na[2] = {ra[0], ra[1]}, nb0[2] = {rb0[0], rb0[1]}, nb1[2] = {rb1[0], rb1[1]};
        if (st < 15) {
#pragma unroll
            for (int j = 0; j < 2; j++) {
                int kk = 2 * st + 2 + j;
                int half = kk >> 4;
                int hoff = (kk & 15) * 16 + aks;
                int kc2 = hoff >> 2;
                if (half == 0) {
                    na[j] = *(const uint2*)(scr + am * SCR_STR + (hoff >> 1));
                    nb0[j] = __ldg((const uint2*)(Wr + (size_t)am * 128) + kc2);
                    nb1[j] = __ldg((const uint2*)(Wr + (size_t)(am + 128) * 128) + kc2);
                } else {
                    na[j] = arow ? __ldg((const uint2*)(g_hh + (size_t)gr * 128) + kc2)
                                 : make_uint2(0u, 0u);
                    nb0[j] = __ldg((const uint2*)(Wo + (size_t)am * 128) + kc2);
                    nb1[j] = __ldg((const uint2*)(Wo + (size_t)(am + 128) * 128) + kc2);
                }
            }
        }
        __syncthreads();
        mma_slab(s0, s0 + ASLAB, wm, wn, lane, c);
        mma_slab(s1, s1 + ASLAB, wm, wn, lane, c);
        ra[0] = na[0]; ra[1] = na[1];
        rb0[0] = nb0[0]; rb0[1] = nb0[1];
        rb1[0] = nb1[0]; rb1[1] = nb1[1];
    }

    // ---- epilogue ----
    float ps[8][2], pq[8][2];
#pragma unroll
    for (int nt = 0; nt < 8; nt++)
        ps[nt][0] = ps[nt][1] = pq[nt][0] = pq[nt][1] = 0.f;

#pragma unroll
    for (int mt = 0; mt < 2; mt++) {
        int row = bm + wm * 32 + mt * 16 + lq;
        bool v0 = row < N_NODES, v1 = (row + 8) < N_NODES;
#pragma unroll
        for (int nt = 0; nt < 8; nt++) {
            int col = wn * 64 + nt * 8 + lr * 2;
            float2 bb = __ldg((const float2*)(br + col));
            float o0 = c[mt][nt][0] + bb.x, o1 = c[mt][nt][1] + bb.y;
            float o2 = c[mt][nt][2] + bb.x, o3 = c[mt][nt][3] + bb.y;
            if (v0) {
                g_outh[(size_t)row * 128 + (col >> 1)] = pack_h2(o0, o1);
                ps[nt][0] += o0; pq[nt][0] += o0 * o0;
                ps[nt][1] += o1; pq[nt][1] += o1 * o1;
            }
            if (v1) {
                g_outh[(size_t)(row + 8) * 128 + (col >> 1)] = pack_h2(o2, o3);
                ps[nt][0] += o2; pq[nt][0] += o2 * o2;
                ps[nt][1] += o3; pq[nt][1] += o3 * o3;
            }
        }
    }
#pragma unroll
    for (int nt = 0; nt < 8; nt++)
#pragma unroll
        for (int u = 0; u < 2; u++) {
#pragma unroll
            for (int d = 4; d < 32; d <<= 1) {
                ps[nt][u] += __shfl_xor_sync(0xffffffffu, ps[nt][u], d);
                pq[nt][u] += __shfl_xor_sync(0xffffffffu, pq[nt][u], d);
            }
        }
    if (lq == 0) {
#pragma unroll
        for (int nt = 0; nt < 8; nt++) {
            int col = wn * 64 + nt * 8 + lr * 2;
            atomicAdd(&stats[col], ps[nt][0]);
            atomicAdd(&stats[col + 1], ps[nt][1]);
            atomicAdd(&stats[HID + col], pq[nt][0]);
            atomicAdd(&stats[HID + col + 1], pq[nt][1]);
        }
    }
}

// =================================================================
// UV precompute: U|V = h @ [W1a;W1b]^T ; grid (391, 2), ny: 0=U 1=V
// =================================================================
__global__ void __launch_bounds__(512, 1)
k_gemm_uv() {
    extern __shared__ uint32_t sm[];
    uint32_t* bufs = sm;
    int tid = threadIdx.x;
    int bm = blockIdx.x * 128;
    int ny = blockIdx.y;
    int lane = tid & 31, lq = lane >> 2, lr = lane & 3;
    int wid = tid >> 5, wm = wid & 3, wn = wid >> 2;
    int am = tid >> 2, aks = (tid & 3) * 4;
    int k2 = aks >> 1;
    int gr = bm + am;
    bool arow = gr < N_NODES;
    float c[2][8][4] = {};

    uint2 ra[2], rb0[2], rb1[2];
#pragma unroll
    for (int j = 0; j < 2; j++) {
        int kc2 = (j * 16 + aks) >> 2;
        ra[j] = arow ? __ldg((const uint2*)(g_hh + (size_t)gr * 128) + kc2)
                     : make_uint2(0u, 0u);
        rb0[j] = __ldg((const uint2*)(g_W116 + (size_t)am * 256) + ny * 64 + kc2);
        rb1[j] = __ldg((const uint2*)(g_W116 + (size_t)(am + 128) * 256) + ny * 64 + kc2);
    }
    for (int st = 0; st < 8; st++) {
        int b = st & 1;
        uint32_t* s0 = bufs + b * 2 * STAGE;
        uint32_t* s1 = s0 + STAGE;
        store_slab(s0, s0 + ASLAB, am, k2, ra[0], rb0[0], rb1[0]);
        store_slab(s1, s1 + ASLAB, am, k2, ra[1], rb0[1], rb1[1]);
        uint2 na[2] = {ra[0], ra[1]}, nb0[2] = {rb0[0], rb0[1]}, nb1[2] = {rb1[0], rb1[1]};
        if (st < 7) {
#pragma unroll
            for (int j = 0; j < 2; j++) {
                int kc2 = ((2 * st + 2 + j) * 16 + aks) >> 2;
                na[j] = arow ? __ldg((const uint2*)(g_hh + (size_t)gr * 128) + kc2)
                             : make_uint2(0u, 0u);
                nb0[j] = __ldg((const uint2*)(g_W116 + (size_t)am * 256) + ny * 64 + kc2);
                nb1[j] = __ldg((const uint2*)(g_W116 + (size_t)(am + 128) * 256) + ny * 64 + kc2);
            }
        }
        __syncthreads();
        mma_slab(s0, s0 + ASLAB, wm, wn, lane, c);
        mma_slab(s1, s1 + ASLAB, wm, wn, lane, c);
        ra[0] = na[0]; ra[1] = na[1];
        rb0[0] = nb0[0]; rb0[1] = nb0[1];
        rb1[0] = nb1[0]; rb1[1] = nb1[1];
    }
#pragma unroll
    for (int mt = 0; mt < 2; mt++) {
        int row = bm + wm * 32 + mt * 16 + lq;
#pragma unroll
        for (int nt = 0; nt < 8; nt++) {
            int col = wn * 64 + nt * 8 + lr * 2;
            if (row < N_NODES)
                g_uv[(size_t)row * 256 + ny * 128 + (col >> 1)] =
                    pack_h2(c[mt][nt][0], c[mt][nt][1]);
            if (row + 8 < N_NODES)
                g_uv[(size_t)(row + 8) * 256 + ny * 128 + (col >> 1)] =
                    pack_h2(c[mt][nt][2], c[mt][nt][3]);
        }
    }
}

// =================================================================
// fused edge MLP: z1 = relu(U[src]+V[dst]+b1) assembled in smem,
// then z1 @ W2^T, dot w3, sigmoid.
// =================================================================
__global__ void __launch_bounds__(512, 1)
k_edge_fused(const int* __restrict__ ei, const float* __restrict__ b1,
             const float* __restrict__ b2, const float* __restrict__ W3,
             const float* __restrict__ b3, float* __restrict__ dout) {
    extern __shared__ uint32_t sm[];
    uint32_t* z1sm = sm;                 // 16 slabs x SL
    uint32_t* bufs = sm + Z1U2;          // 4 x BSLAB
    __shared__ float sred[4][128];
    int tid = threadIdx.x;
    int bm = blockIdx.x * 128;
    int lane = tid & 31, lq = lane >> 2, lr = lane & 3;
    int wid = tid >> 5, wm = wid & 3, wn = wid >> 2;
    int am = tid >> 2, aks = (tid & 3) * 4;
    int k2 = aks >> 1;

    // ---- stage 0: assemble z1 in fragment layout ----
    {
        int row = tid >> 2, sub = tid & 3;
        int e = bm + row;
        bool val = e < N_EDGES;
        int nsrc = val ? __ldg(ei + e) : 0;
        int ndst = val ? __ldg(ei + N_EDGES + e) : 0;
        const uint4* up = (const uint4*)(g_uv + (size_t)nsrc * 256);
        const uint4* vp = (const uint4*)(g_uv + (size_t)ndst * 256 + 128);
#pragma unroll
        for (int q = 0; q < 4; q++) {
            int c2b = q * 32 + sub * 8;          // half2 col base
            uint4 u0 = __ldg(up + (c2b >> 2));
            uint4 u1 = __ldg(up + (c2b >> 2) + 1);
            uint4 v0 = __ldg(vp + (c2b >> 2));
            uint4 v1 = __ldg(vp + (c2b >> 2) + 1);
            uint32_t uu[8] = {u0.x, u0.y, u0.z, u0.w, u1.x, u1.y, u1.z, u1.w};
            uint32_t vv[8] = {v0.x, v0.y, v0.z, v0.w, v1.x, v1.y, v1.z, v1.w};
            uint32_t* dst = z1sm + (q * 4 + sub) * SL + row;
#pragma unroll
            for (int j = 0; j < 8; j++) {
                int c2 = c2b + j;
                float2 fu = unpack_h2(uu[j]);
                float2 fv = unpack_h2(vv[j]);
                float2 bb = __ldg((const float2*)b1 + c2);
                dst[j * ASTR2] = pack_h2(fmaxf(fu.x + fv.x + bb.x, 0.f),
                                         fmaxf(fu.y + fv.y + bb.y, 0.f));
            }
        }
    }
    __syncthreads();

    // ---- stage 2: z1 @ W2^T (BK=32, B double-buffered) ----
    float c[2][8][4] = {};
    uint2 qb0[2], qb1[2];
#pragma unroll
    for (int j = 0; j < 2; j++) {
        int kc2 = (j * 16 + aks) >> 2;
        qb0[j] = __ldg((const uint2*)(g_W216 + (size_t)am * 128) + kc2);
        qb1[j] = __ldg((const uint2*)(g_W216 + (size_t)(am + 128) * 128) + kc2);
    }
    for (int st = 0; st < 8; st++) {
        int b = st & 1;
        uint32_t* B0 = bufs + b * 2 * BSLAB;
        uint32_t* B1 = B0 + BSLAB;
        store_slab_b(B0, am, k2, qb0[0], qb1[0]);
        store_slab_b(B1, am, k2, qb0[1], qb1[1]);
        uint2 n0[2] = {qb0[0], qb0[1]}, n1[2] = {qb1[0], qb1[1]};
        if (st < 7) {
#pragma unroll
            for (int j = 0; j < 2; j++) {
                int kc2 = ((2 * st + 2 + j) * 16 + aks) >> 2;
                n0[j] = __ldg((const uint2*)(g_W216 + (size_t)am * 128) + kc2);
                n1[j] = __ldg((const uint2*)(g_W216 + (size_t)(am + 128) * 128) + kc2);
            }
        }
        __syncthreads();
        mma_slab(z1sm + (2 * st) * SL, B0, wm, wn, lane, c);
        mma_slab(z1sm + (2 * st + 1) * SL, B1, wm, wn, lane, c);
        qb0[0] = n0[0]; qb0[1] = n0[1];
        qb1[0] = n1[0]; qb1[1] = n1[1];
    }

#pragma unroll
    for (int mt = 0; mt < 2; mt++) {
        float p0 = 0.f, p1 = 0.f;
#pragma unroll
        for (int nt = 0; nt < 8; nt++) {
            int col = wn * 64 + nt * 8 + lr * 2;
            float2 bb = __ldg((const float2*)(b2 + col));
            float2 ww = __ldg((const float2*)(W3 + col));
            p0 = fmaf(fmaxf(c[mt][nt][0] + bb.x, 0.f), ww.x, p0);
            p0 = fmaf(fmaxf(c[mt][nt][1] + bb.y, 0.f), ww.y, p0);
            p1 = fmaf(fmaxf(c[mt][nt][2] + bb.x, 0.f), ww.x, p1);
            p1 = fmaf(fmaxf(c[mt][nt][3] + bb.y, 0.f), ww.y, p1);
        }
        p0 += __shfl_xor_sync(0xffffffffu, p0, 1);
        p0 += __shfl_xor_sync(0xffffffffu, p0, 2);
        p1 += __shfl_xor_sync(0xffffffffu, p1, 1);
        p1 += __shfl_xor_sync(0xffffffffu, p1, 2);
        if (lr == 0) {
            sred[wn][wm * 32 + mt * 16 + lq] = p0;
            sred[wn][wm * 32 + mt * 16 + lq + 8] = p1;
        }
    }
    __syncthreads();
    if (tid < 128) {
        int gr = bm + tid;
        if (gr < N_EDGES) {
            float s = sred[0][tid] + sred[1][tid] + sred[2][tid] + sred[3][tid] + __ldg(b3);
            dout[gr] = 1.f / (1.f + expf(-s));
        }
    }
}

// ---------------------------------------------------------------- launch
extern "C" void kernel_launch(void* const* d_in, const int* in_sizes, int n_in,
                              void* d_out, int out_size) {
    const float* x     = (const float*)d_in[0];
    const int*   ei    = (const int*)  d_in[1];
    const float* Win   = (const float*)d_in[2];
    const float* Wrel  = (const float*)d_in[3];
    const float* brel  = (const float*)d_in[4];
    const float* Wroot = (const float*)d_in[5];
    const float* gamma = (const float*)d_in[6];
    const float* beta  = (const float*)d_in[7];
    const float* W1    = (const float*)d_in[8];
    const float* b1    = (const float*)d_in[9];
    const float* W2    = (const float*)d_in[10];
    const float* b2    = (const float*)d_in[11];
    const float* W3    = (const float*)d_in[12];
    const float* b3    = (const float*)d_in[13];
    float* out = (float*)d_out;

    cudaFuncSetAttribute(k_gemm_node, cudaFuncAttributeMaxDynamicSharedMemorySize, NSMEM);
    cudaFuncSetAttribute(k_gemm_uv,   cudaFuncAttributeMaxDynamicSharedMemorySize, UVSMEM);
    cudaFuncSetAttribute(k_edge_fused, cudaFuncAttributeMaxDynamicSharedMemorySize, ESMEM);

    int ncvt = LAYERS * 256 * 128 + 256 * 256 + 256 * 128;
    k_cvt_weights<<<(ncvt + 255) / 256, 256>>>(Wrel, Wroot, W1, W2);
    k_input_fc<<<(N_NODES * 128 + 255) / 256, 256>>>(x, Win);
    k_csr_count<<<(N_EDGES + 255) / 256, 256>>>(ei);
    k_csr_scan<<<1, 1024>>>();
    k_csr_fill<<<(N_EDGES + 255) / 256, 256>>>(ei);

    int node_grid = (N_NODES + 127) / 128;     // 391
    for (int l = 0; l < LAYERS; l++) {
        k_gemm_node<<<node_grid, 512, NSMEM>>>(l, brel + (size_t)l * HID);
        k_bn_apply<<<(N_NODES * 128 + 255) / 256, 256>>>(
            l, gamma + (size_t)l * HID, beta + (size_t)l * HID);
    }

    dim3 uv_grid(node_grid, 2);
    k_gemm_uv<<<uv_grid, 512, UVSMEM>>>();
    int edge_grid = (N_EDGES + 127) / 128;     // 3907
    k_edge_fused<<<edge_grid, 512, ESMEM>>>(ei, b1, b2, W3, b3, out);
}